// round 5
// baseline (speedup 1.0000x reference)
#include <cuda_runtime.h>
#include <cuda_bf16.h>
#include <cstdint>

#define BS 2
#define NQ 10000
#define NV 19560
#define EMBED 256
#define NH 8
#define HD 32
#define NROWS (BS*NQ)           // 20000
#define VROWS (BS*NV)           // 39120

// Level constants (static per reference)
__device__ __constant__ int c_Hl[4]    = {92, 46, 23, 12};
__device__ __constant__ int c_Wl[4]    = {160, 80, 40, 20};
__device__ __constant__ int c_start[4] = {0, 14720, 18400, 19320};

// Scratch (allocation-free contract -> device globals)
__device__ float g_v[(size_t)VROWS * EMBED];        // projected value [b][n][h][d]
__device__ float g_coord[(size_t)NROWS * 256];      // [row][h][l][p][{x,y}]
__device__ float g_attn[(size_t)NROWS * NH * 16];   // softmaxed weights [row][h][l*4+p]

// ---------------------------------------------------------------------------
// Kernel A: q = query+query_pos; off = q@W_off+b_off; attn = softmax(q@W_attn+b_attn)
// emits final pixel coords and attention weights.
// 8 query-rows per block, 256 threads.
// ---------------------------------------------------------------------------
__global__ __launch_bounds__(256)
void k_offattn(const float* __restrict__ query, const float* __restrict__ qpos,
               const float* __restrict__ refp,
               const float* __restrict__ Woff, const float* __restrict__ boff,
               const float* __restrict__ Wattn, const float* __restrict__ battn)
{
    __shared__ float sq[8][EMBED];
    __shared__ float slog[8][128];
    const int row0 = blockIdx.x * 8;
    const int t = threadIdx.x;

    #pragma unroll
    for (int r = 0; r < 8; r++) {
        int row = row0 + r;
        sq[r][t] = query[(size_t)row * EMBED + t] + qpos[(size_t)row * EMBED + t];
    }
    __syncthreads();

    // sampling-offset column t for all 8 rows
    float acc[8];
    #pragma unroll
    for (int r = 0; r < 8; r++) acc[r] = boff[t];
    for (int k = 0; k < EMBED; k++) {
        float w = Woff[(size_t)k * 256 + t];
        #pragma unroll
        for (int r = 0; r < 8; r++) acc[r] += sq[r][k] * w;
    }

    // attention logits: threads 0..127 own one of 128 columns
    if (t < 128) {
        float la[8];
        #pragma unroll
        for (int r = 0; r < 8; r++) la[r] = battn[t];
        for (int k = 0; k < EMBED; k++) {
            float w = Wattn[(size_t)k * 128 + t];
            #pragma unroll
            for (int r = 0; r < 8; r++) la[r] += sq[r][k] * w;
        }
        #pragma unroll
        for (int r = 0; r < 8; r++) slog[r][t] = la[r];
    }
    __syncthreads();

    // softmax over 16 per (row, head): 64 groups
    if (t < 64) {
        int r = t >> 3, h = t & 7;
        float* p = &slog[r][h * 16];
        float m = -1e30f;
        #pragma unroll
        for (int i = 0; i < 16; i++) m = fmaxf(m, p[i]);
        float s = 0.f;
        #pragma unroll
        for (int i = 0; i < 16; i++) { float e = __expf(p[i] - m); p[i] = e; s += e; }
        float inv = 1.f / s;
        int row = row0 + r;
        #pragma unroll
        for (int i = 0; i < 16; i++)
            g_attn[((size_t)row * NH + h) * 16 + i] = p[i] * inv;
    }

    // coords: col t = h*32 + l*8 + p*2 + c ; x = ref_x*W + off_x - 0.5
    {
        int c = t & 1, p = (t >> 1) & 3, l = (t >> 3) & 3;   // FIXED: l from bits [3:5)
        float norm = (c == 0) ? (float)c_Wl[l] : (float)c_Hl[l];
        #pragma unroll
        for (int r = 0; r < 8; r++) {
            int row = row0 + r;
            float rv = refp[((size_t)row * 4 + p) * 2 + c];
            g_coord[(size_t)row * 256 + t] = rv * norm + acc[r] - 0.5f;
        }
    }
}

// ---------------------------------------------------------------------------
// Kernel B: value projection v = value @ W_val + b_val  (39120 x 256 x 256)
// 16 rows per block, 256 threads, thread owns output column t.
// ---------------------------------------------------------------------------
__global__ __launch_bounds__(256)
void k_vproj(const float* __restrict__ value, const float* __restrict__ Wv,
             const float* __restrict__ bv)
{
    __shared__ float sv[16][EMBED];
    const int row0 = blockIdx.x * 16;
    const int t = threadIdx.x;

    #pragma unroll
    for (int r = 0; r < 16; r++)
        sv[r][t] = value[(size_t)(row0 + r) * EMBED + t];
    __syncthreads();

    float acc[16];
    #pragma unroll
    for (int r = 0; r < 16; r++) acc[r] = 0.f;
    for (int k = 0; k < EMBED; k++) {
        float w = Wv[(size_t)k * 256 + t];
        #pragma unroll
        for (int r = 0; r < 16; r++) acc[r] += sv[r][k] * w;
    }
    float bias = bv[t];
    #pragma unroll
    for (int r = 0; r < 16; r++)
        g_v[(size_t)(row0 + r) * 256 + t] = acc[r] + bias;
}

// ---------------------------------------------------------------------------
// Kernel C: bilinear sampling + weighted reduce.
// One block per (b,q); warp = head; lane = channel d.
// ---------------------------------------------------------------------------
__global__ __launch_bounds__(256)
void k_sample(float* __restrict__ out)
{
    const int bq = blockIdx.x;            // 0..19999
    const int h = threadIdx.x >> 5;
    const int lane = threadIdx.x & 31;
    const int b = bq / NQ;

    const float* __restrict__ coord = &g_coord[(size_t)bq * 256 + h * 32];
    const float* __restrict__ aw = &g_attn[((size_t)bq * NH + h) * 16];

    float acc = 0.f;
    #pragma unroll
    for (int l = 0; l < 4; l++) {
        const int H = c_Hl[l], W = c_Wl[l];
        const float* __restrict__ vbase =
            &g_v[((size_t)(b * NV + c_start[l])) * 256 + h * 32 + lane];
        #pragma unroll
        for (int p = 0; p < 4; p++) {
            float x = coord[l * 8 + p * 2 + 0];
            float y = coord[l * 8 + p * 2 + 1];
            float w = aw[l * 4 + p];
            float x0f = floorf(x), y0f = floorf(y);
            int x0 = (int)x0f, y0 = (int)y0f;
            float wx1 = x - x0f, wy1 = y - y0f;
            float wx0 = 1.f - wx1, wy0 = 1.f - wy1;

            bool xin0 = (x0 >= 0) & (x0 < W);
            bool xin1 = (x0 >= -1) & (x0 < W - 1);
            bool yin0 = (y0 >= 0) & (y0 < H);
            bool yin1 = (y0 >= -1) & (y0 < H - 1);

            float v00 = 0.f, v01 = 0.f, v10 = 0.f, v11 = 0.f;
            if (yin0) {
                const float* rowp = vbase + (size_t)y0 * W * 256;
                if (xin0) v00 = rowp[(size_t)x0 * 256];
                if (xin1) v01 = rowp[(size_t)(x0 + 1) * 256];
            }
            if (yin1) {
                const float* rowp = vbase + (size_t)(y0 + 1) * W * 256;
                if (xin0) v10 = rowp[(size_t)x0 * 256];
                if (xin1) v11 = rowp[(size_t)(x0 + 1) * 256];
            }
            acc += w * (v00 * (wy0 * wx0) + v01 * (wy0 * wx1)
                      + v10 * (wy1 * wx0) + v11 * (wy1 * wx1));
        }
    }
    out[(size_t)bq * 256 + h * 32 + lane] = acc;
}

// ---------------------------------------------------------------------------
extern "C" void kernel_launch(void* const* d_in, const int* in_sizes, int n_in,
                              void* d_out, int out_size)
{
    const float* query = (const float*)d_in[0];
    const float* value = (const float*)d_in[1];
    const float* qpos  = (const float*)d_in[2];
    const float* refp  = (const float*)d_in[3];
    const float* Wval  = (const float*)d_in[4];
    const float* bval  = (const float*)d_in[5];
    const float* Woff  = (const float*)d_in[6];
    const float* boff  = (const float*)d_in[7];
    const float* Wattn = (const float*)d_in[8];
    const float* battn = (const float*)d_in[9];
    float* out = (float*)d_out;

    k_vproj<<<VROWS / 16, 256>>>(value, Wval, bval);
    k_offattn<<<NROWS / 8, 256>>>(query, qpos, refp, Woff, boff, Wattn, battn);
    k_sample<<<NROWS, 256>>>(out);
}

// round 8
// speedup vs baseline: 1.7411x; 1.7411x over previous
#include <cuda_runtime.h>
#include <cuda_bf16.h>
#include <cstdint>

#define BS 2
#define NQ 10000
#define NV 19560
#define EMBED 256
#define NH 8
#define HD 32
#define NROWS (BS*NQ)           // 20000
#define VROWS (BS*NV)           // 39120

__device__ __constant__ int c_Hl[4]    = {92, 46, 23, 12};
__device__ __constant__ int c_Wl[4]    = {160, 80, 40, 20};
__device__ __constant__ int c_start[4] = {0, 14720, 18400, 19320};

__device__ float g_v[(size_t)VROWS * EMBED];
__device__ float g_coord[(size_t)NROWS * 256];
__device__ float g_attn[(size_t)NROWS * NH * 16];

#define PACK2(d, lo, hi) asm("mov.b64 %0, {%1, %2};" : "=l"(d) : "f"(lo), "f"(hi))
#define UNPACK2(lo, hi, d) asm("mov.b64 {%0, %1}, %2;" : "=f"(lo), "=f"(hi) : "l"(d))
#define FFMA2(c, a, b) asm("fma.rn.f32x2 %0, %1, %2, %0;" : "+l"(c) : "l"(a), "l"(b))

// ---------------------------------------------------------------------------
// Kernel A: q = query+query_pos; off = q@W_off+b_off; attn = softmax(q@W_attn+b_attn)
// 16 rows per block (grid 1250), 256 threads, f32x2 packed row-pair FMA.
// smem: sq[k][row] transposed (20 KB) + slog (8 KB) = 28 KB < 48 KB.
// ---------------------------------------------------------------------------
__global__ __launch_bounds__(256)
void k_offattn(const float* __restrict__ query, const float* __restrict__ qpos,
               const float* __restrict__ refp,
               const float* __restrict__ Woff, const float* __restrict__ boff,
               const float* __restrict__ Wattn, const float* __restrict__ battn)
{
    __shared__ float sq[256][20];     // [k][row], pad 20 -> 80B stride (16B aligned)
    __shared__ float slog[16][128];   // attn logits
    const int row0 = blockIdx.x * 16;
    const int t = threadIdx.x;

    #pragma unroll
    for (int r = 0; r < 16; r++) {
        size_t idx = (size_t)(row0 + r) * EMBED + t;
        sq[t][r] = query[idx] + qpos[idx];
    }
    __syncthreads();

    // ---- Phase 1: sampling-offset GEMM, col t, 16 rows as 8 f32x2 pairs ----
    unsigned long long acc[8];
    {
        float b = boff[t];
        unsigned long long binit; PACK2(binit, b, b);
        #pragma unroll
        for (int i = 0; i < 8; i++) acc[i] = binit;
    }
    #pragma unroll 4
    for (int k = 0; k < 256; k++) {
        float w = Woff[(size_t)k * 256 + t];
        unsigned long long w2; PACK2(w2, w, w);
        #pragma unroll
        for (int i = 0; i < 4; i++) {
            ulonglong2 s = *reinterpret_cast<const ulonglong2*>(&sq[k][4 * i]);
            FFMA2(acc[2 * i], s.x, w2);
            FFMA2(acc[2 * i + 1], s.y, w2);
        }
    }

    // ---- coords: col t = h*32 + l*8 + p*2 + c ; x = ref*W + off - 0.5 ----
    {
        int c = t & 1, p = (t >> 1) & 3, l = (t >> 3) & 3;
        float norm = (c == 0) ? (float)c_Wl[l] : (float)c_Hl[l];
        #pragma unroll
        for (int i = 0; i < 8; i++) {
            float lo, hi; UNPACK2(lo, hi, acc[i]);
            int r = 2 * i;
            float rv0 = refp[((size_t)(row0 + r) * 4 + p) * 2 + c];
            float rv1 = refp[((size_t)(row0 + r + 1) * 4 + p) * 2 + c];
            g_coord[(size_t)(row0 + r) * 256 + t]     = rv0 * norm + lo - 0.5f;
            g_coord[(size_t)(row0 + r + 1) * 256 + t] = rv1 * norm + hi - 0.5f;
        }
    }

    // ---- Phase 2: attention-logit GEMM: col = t&127, 8 rows per thread half ----
    {
        const int col = t & 127;
        const int rbase = (t >> 7) * 8;         // rows rbase..rbase+7
        unsigned long long la[4];
        {
            float b = battn[col];
            unsigned long long binit; PACK2(binit, b, b);
            #pragma unroll
            for (int i = 0; i < 4; i++) la[i] = binit;
        }
        #pragma unroll 4
        for (int k = 0; k < 256; k++) {
            float w = Wattn[(size_t)k * 128 + col];
            unsigned long long w2; PACK2(w2, w, w);
            #pragma unroll
            for (int i = 0; i < 2; i++) {
                ulonglong2 s = *reinterpret_cast<const ulonglong2*>(&sq[k][rbase + 4 * i]);
                FFMA2(la[2 * i], s.x, w2);
                FFMA2(la[2 * i + 1], s.y, w2);
            }
        }
        #pragma unroll
        for (int i = 0; i < 4; i++) {
            float lo, hi; UNPACK2(lo, hi, la[i]);
            slog[rbase + 2 * i][col] = lo;
            slog[rbase + 2 * i + 1][col] = hi;
        }
    }
    __syncthreads();

    // ---- softmax over 16 per (row, head): 128 groups on threads 0..127 ----
    if (t < 128) {
        int r = t >> 3, h = t & 7;
        float* p = &slog[r][h * 16];
        float m = -1e30f;
        #pragma unroll
        for (int i = 0; i < 16; i++) m = fmaxf(m, p[i]);
        float s = 0.f;
        float e[16];
        #pragma unroll
        for (int i = 0; i < 16; i++) { e[i] = __expf(p[i] - m); s += e[i]; }
        float inv = 1.f / s;
        int row = row0 + r;
        #pragma unroll
        for (int i = 0; i < 16; i++)
            g_attn[((size_t)row * NH + h) * 16 + i] = e[i] * inv;
    }
}

// ---------------------------------------------------------------------------
// Kernel B: value projection (39120 x 256 x 256), 32 rows/block, f32x2 FMA.
// smem 36,864 B (< 48 KB).
// ---------------------------------------------------------------------------
__global__ __launch_bounds__(256)
void k_vproj(const float* __restrict__ value, const float* __restrict__ Wv,
             const float* __restrict__ bv)
{
    __shared__ float sv[256][36];    // [k][row], 144B stride (16B aligned)
    const int row0 = blockIdx.x * 32;
    const int t = threadIdx.x;

    #pragma unroll
    for (int r = 0; r < 32; r++) {
        int row = row0 + r;
        sv[t][r] = (row < VROWS) ? value[(size_t)row * EMBED + t] : 0.f;
    }
    __syncthreads();

    unsigned long long acc[16];
    {
        float b = bv[t];
        unsigned long long binit; PACK2(binit, b, b);
        #pragma unroll
        for (int i = 0; i < 16; i++) acc[i] = binit;
    }
    #pragma unroll 4
    for (int k = 0; k < 256; k++) {
        float w = Wv[(size_t)k * 256 + t];
        unsigned long long w2; PACK2(w2, w, w);
        #pragma unroll
        for (int i = 0; i < 8; i++) {
            ulonglong2 s = *reinterpret_cast<const ulonglong2*>(&sv[k][4 * i]);
            FFMA2(acc[2 * i], s.x, w2);
            FFMA2(acc[2 * i + 1], s.y, w2);
        }
    }
    #pragma unroll
    for (int i = 0; i < 16; i++) {
        float lo, hi; UNPACK2(lo, hi, acc[i]);
        int r = row0 + 2 * i;
        if (r < VROWS)     g_v[(size_t)r * 256 + t] = lo;
        if (r + 1 < VROWS) g_v[(size_t)(r + 1) * 256 + t] = hi;
    }
}

// ---------------------------------------------------------------------------
// Kernel C: bilinear sampling + weighted reduce (unchanged).
// One block per (b,q); warp = head; lane = channel d.
// ---------------------------------------------------------------------------
__global__ __launch_bounds__(256)
void k_sample(float* __restrict__ out)
{
    const int bq = blockIdx.x;
    const int h = threadIdx.x >> 5;
    const int lane = threadIdx.x & 31;
    const int b = bq / NQ;

    const float* __restrict__ coord = &g_coord[(size_t)bq * 256 + h * 32];
    const float* __restrict__ aw = &g_attn[((size_t)bq * NH + h) * 16];

    float acc = 0.f;
    #pragma unroll
    for (int l = 0; l < 4; l++) {
        const int H = c_Hl[l], W = c_Wl[l];
        const float* __restrict__ vbase =
            &g_v[((size_t)(b * NV + c_start[l])) * 256 + h * 32 + lane];
        #pragma unroll
        for (int p = 0; p < 4; p++) {
            float x = coord[l * 8 + p * 2 + 0];
            float y = coord[l * 8 + p * 2 + 1];
            float w = aw[l * 4 + p];
            float x0f = floorf(x), y0f = floorf(y);
            int x0 = (int)x0f, y0 = (int)y0f;
            float wx1 = x - x0f, wy1 = y - y0f;
            float wx0 = 1.f - wx1, wy0 = 1.f - wy1;

            bool xin0 = (x0 >= 0) & (x0 < W);
            bool xin1 = (x0 >= -1) & (x0 < W - 1);
            bool yin0 = (y0 >= 0) & (y0 < H);
            bool yin1 = (y0 >= -1) & (y0 < H - 1);

            float v00 = 0.f, v01 = 0.f, v10 = 0.f, v11 = 0.f;
            if (yin0) {
                const float* rowp = vbase + (size_t)y0 * W * 256;
                if (xin0) v00 = rowp[(size_t)x0 * 256];
                if (xin1) v01 = rowp[(size_t)(x0 + 1) * 256];
            }
            if (yin1) {
                const float* rowp = vbase + (size_t)(y0 + 1) * W * 256;
                if (xin0) v10 = rowp[(size_t)x0 * 256];
                if (xin1) v11 = rowp[(size_t)(x0 + 1) * 256];
            }
            acc += w * (v00 * (wy0 * wx0) + v01 * (wy0 * wx1)
                      + v10 * (wy1 * wx0) + v11 * (wy1 * wx1));
        }
    }
    out[(size_t)bq * 256 + h * 32 + lane] = acc;
}

// ---------------------------------------------------------------------------
extern "C" void kernel_launch(void* const* d_in, const int* in_sizes, int n_in,
                              void* d_out, int out_size)
{
    const float* query = (const float*)d_in[0];
    const float* value = (const float*)d_in[1];
    const float* qpos  = (const float*)d_in[2];
    const float* refp  = (const float*)d_in[3];
    const float* Wval  = (const float*)d_in[4];
    const float* bval  = (const float*)d_in[5];
    const float* Woff  = (const float*)d_in[6];
    const float* boff  = (const float*)d_in[7];
    const float* Wattn = (const float*)d_in[8];
    const float* battn = (const float*)d_in[9];
    float* out = (float*)d_out;

    k_vproj<<<(VROWS + 31) / 32, 256>>>(value, Wval, bval);
    k_offattn<<<NROWS / 16, 256>>>(query, qpos, refp, Woff, boff, Wattn, battn);
    k_sample<<<NROWS, 256>>>(out);
}

// round 9
// speedup vs baseline: 2.1398x; 1.2290x over previous
#include <cuda_runtime.h>
#include <cuda_bf16.h>
#include <cstdint>

#define BS 2
#define NQ 10000
#define NV 19560
#define EMBED 256
#define NH 8
#define HD 32
#define NROWS (BS*NQ)           // 20000
#define VROWS (BS*NV)           // 39120

__device__ __constant__ int c_Hl[4]    = {92, 46, 23, 12};
__device__ __constant__ int c_Wl[4]    = {160, 80, 40, 20};
__device__ __constant__ int c_start[4] = {0, 14720, 18400, 19320};

__device__ float g_v[(size_t)VROWS * EMBED];
__device__ float g_coord[(size_t)NROWS * 256];
__device__ float g_attn[(size_t)NROWS * NH * 16];

#define PACK2(d, lo, hi) asm("mov.b64 %0, {%1, %2};" : "=l"(d) : "f"(lo), "f"(hi))
#define UNPACK2(lo, hi, d) asm("mov.b64 {%0, %1}, %2;" : "=f"(lo), "=f"(hi) : "l"(d))
#define FFMA2(c, a, b) asm("fma.rn.f32x2 %0, %1, %2, %0;" : "+l"(c) : "l"(a), "l"(b))

// ---------------------------------------------------------------------------
// Kernel B: value projection, register-tiled: block = 64 rows x 128 cols,
// thread = 8 rows x 4 cols, k-chunks of 32. smem: sA 8.7KB + sW 16.9KB.
// ---------------------------------------------------------------------------
__global__ __launch_bounds__(256)
void k_vproj(const float* __restrict__ value, const float* __restrict__ Wv,
             const float* __restrict__ bv)
{
    __shared__ float sA[32][68];    // [k][row], stride 68 (16B aligned, 4-way store conflict)
    __shared__ float sW[32][132];   // [k][col]
    const int t = threadIdx.x;
    const int tx = t & 31, ty = t >> 5;
    const int row0 = (blockIdx.x >> 1) * 64;
    const int col0 = (blockIdx.x & 1) * 128;
    const int myrow = row0 + ty * 8;
    const int mycol = col0 + tx * 4;

    unsigned long long acc[16];
    #pragma unroll
    for (int c = 0; c < 4; c++) {
        float b = bv[mycol + c];
        unsigned long long b2; PACK2(b2, b, b);
        acc[c*4+0] = b2; acc[c*4+1] = b2; acc[c*4+2] = b2; acc[c*4+3] = b2;
    }

    for (int kc = 0; kc < 256; kc += 32) {
        #pragma unroll
        for (int rr = 0; rr < 8; rr++) {
            int r = rr * 8 + ty;
            int row = row0 + r;
            sA[tx][r] = (row < VROWS) ? value[(size_t)row * 256 + kc + tx] : 0.f;
        }
        #pragma unroll
        for (int i = 0; i < 16; i++) {
            int kk = (t >> 7) + i * 2;
            int cc = t & 127;
            sW[kk][cc] = Wv[(size_t)(kc + kk) * 256 + col0 + cc];
        }
        __syncthreads();

        #pragma unroll
        for (int k = 0; k < 32; k++) {
            ulonglong2 a01 = *reinterpret_cast<const ulonglong2*>(&sA[k][ty*8]);
            ulonglong2 a23 = *reinterpret_cast<const ulonglong2*>(&sA[k][ty*8+4]);
            float4 w = *reinterpret_cast<const float4*>(&sW[k][tx*4]);
            unsigned long long w2[4];
            PACK2(w2[0], w.x, w.x); PACK2(w2[1], w.y, w.y);
            PACK2(w2[2], w.z, w.z); PACK2(w2[3], w.w, w.w);
            #pragma unroll
            for (int c = 0; c < 4; c++) {
                FFMA2(acc[c*4+0], a01.x, w2[c]);
                FFMA2(acc[c*4+1], a01.y, w2[c]);
                FFMA2(acc[c*4+2], a23.x, w2[c]);
                FFMA2(acc[c*4+3], a23.y, w2[c]);
            }
        }
        __syncthreads();
    }

    #pragma unroll
    for (int rp = 0; rp < 4; rp++) {
        float o0[4], o1[4];
        #pragma unroll
        for (int c = 0; c < 4; c++) { UNPACK2(o0[c], o1[c], acc[c*4+rp]); }
        int row = myrow + rp * 2;
        if (row < VROWS)
            *reinterpret_cast<float4*>(&g_v[(size_t)row*256 + mycol]) =
                make_float4(o0[0], o0[1], o0[2], o0[3]);
        if (row + 1 < VROWS)
            *reinterpret_cast<float4*>(&g_v[(size_t)(row+1)*256 + mycol]) =
                make_float4(o1[0], o1[1], o1[2], o1[3]);
    }
}

// ---------------------------------------------------------------------------
// Kernel A: fused offsets+attn GEMM, register-tiled. Grid = 313 rowblks x 3
// colblks (cb 0,1 = offset cols 0..255; cb 2 = attn cols 0..127).
// Epilogues fused: coord decode (cb<2), 4-lane-shfl softmax (cb==2).
// ---------------------------------------------------------------------------
__global__ __launch_bounds__(256)
void k_offattn(const float* __restrict__ query, const float* __restrict__ qpos,
               const float* __restrict__ refp,
               const float* __restrict__ Woff, const float* __restrict__ boff,
               const float* __restrict__ Wattn, const float* __restrict__ battn)
{
    __shared__ float sA[32][68];
    __shared__ float sW[32][132];
    const int t = threadIdx.x;
    const int tx = t & 31, ty = t >> 5;
    const int cb = blockIdx.x % 3;
    const int row0 = (blockIdx.x / 3) * 64;
    const int myrow = row0 + ty * 8;

    const bool is_attn = (cb == 2);
    const int col0 = is_attn ? 0 : cb * 128;
    const float* __restrict__ Wm = is_attn ? Wattn : Woff;
    const float* __restrict__ bm = is_attn ? battn : boff;
    const int ldw = is_attn ? 128 : 256;
    const int mycol = col0 + tx * 4;

    unsigned long long acc[16];
    #pragma unroll
    for (int c = 0; c < 4; c++) {
        float b = bm[mycol + c];
        unsigned long long b2; PACK2(b2, b, b);
        acc[c*4+0] = b2; acc[c*4+1] = b2; acc[c*4+2] = b2; acc[c*4+3] = b2;
    }

    for (int kc = 0; kc < 256; kc += 32) {
        #pragma unroll
        for (int rr = 0; rr < 8; rr++) {
            int r = rr * 8 + ty;
            int row = row0 + r;
            float v = 0.f;
            if (row < NROWS) {
                size_t idx = (size_t)row * 256 + kc + tx;
                v = query[idx] + qpos[idx];
            }
            sA[tx][r] = v;
        }
        #pragma unroll
        for (int i = 0; i < 16; i++) {
            int kk = (t >> 7) + i * 2;
            int cc = t & 127;
            sW[kk][cc] = Wm[(size_t)(kc + kk) * ldw + col0 + cc];
        }
        __syncthreads();

        #pragma unroll
        for (int k = 0; k < 32; k++) {
            ulonglong2 a01 = *reinterpret_cast<const ulonglong2*>(&sA[k][ty*8]);
            ulonglong2 a23 = *reinterpret_cast<const ulonglong2*>(&sA[k][ty*8+4]);
            float4 w = *reinterpret_cast<const float4*>(&sW[k][tx*4]);
            unsigned long long w2[4];
            PACK2(w2[0], w.x, w.x); PACK2(w2[1], w.y, w.y);
            PACK2(w2[2], w.z, w.z); PACK2(w2[3], w.w, w.w);
            #pragma unroll
            for (int c = 0; c < 4; c++) {
                FFMA2(acc[c*4+0], a01.x, w2[c]);
                FFMA2(acc[c*4+1], a01.y, w2[c]);
                FFMA2(acc[c*4+2], a23.x, w2[c]);
                FFMA2(acc[c*4+3], a23.y, w2[c]);
            }
        }
        __syncthreads();
    }

    // unpack: o[r][c] for 8 rows x 4 cols
    float o[8][4];
    #pragma unroll
    for (int rp = 0; rp < 4; rp++)
        #pragma unroll
        for (int c = 0; c < 4; c++)
            UNPACK2(o[rp*2][c], o[rp*2+1][c], acc[c*4+rp]);

    if (!is_attn) {
        // coord epilogue: col = mycol + c in [0,256): h*32+l*8+p*2+cc
        #pragma unroll
        for (int c = 0; c < 4; c++) {
            int col = mycol + c;
            int cc = col & 1, p = (col >> 1) & 3, l = (col >> 3) & 3;
            float norm = (cc == 0) ? (float)c_Wl[l] : (float)c_Hl[l];
            #pragma unroll
            for (int r = 0; r < 8; r++) {
                int row = myrow + r;
                if (row < NROWS) {
                    float rv = refp[((size_t)row * 4 + p) * 2 + cc];
                    g_coord[(size_t)row * 256 + col] = rv * norm + o[r][c] - 0.5f;
                }
            }
        }
    } else {
        // softmax epilogue: head = tx>>2; group of 4 lanes holds the 16 logits
        const int head = tx >> 2, sub = tx & 3;
        #pragma unroll
        for (int r = 0; r < 8; r++) {
            float m = fmaxf(fmaxf(o[r][0], o[r][1]), fmaxf(o[r][2], o[r][3]));
            m = fmaxf(m, __shfl_xor_sync(0xffffffffu, m, 1));
            m = fmaxf(m, __shfl_xor_sync(0xffffffffu, m, 2));
            float e[4], s = 0.f;
            #pragma unroll
            for (int c = 0; c < 4; c++) { e[c] = __expf(o[r][c] - m); s += e[c]; }
            s += __shfl_xor_sync(0xffffffffu, s, 1);
            s += __shfl_xor_sync(0xffffffffu, s, 2);
            float inv = 1.f / s;
            int row = myrow + r;
            if (row < NROWS) {
                #pragma unroll
                for (int c = 0; c < 4; c++)
                    g_attn[((size_t)row * NH + head) * 16 + sub * 4 + c] = e[c] * inv;
            }
        }
    }
}

// ---------------------------------------------------------------------------
// Kernel C: bilinear sampling + weighted reduce (unchanged).
// ---------------------------------------------------------------------------
__global__ __launch_bounds__(256)
void k_sample(float* __restrict__ out)
{
    const int bq = blockIdx.x;
    const int h = threadIdx.x >> 5;
    const int lane = threadIdx.x & 31;
    const int b = bq / NQ;

    const float* __restrict__ coord = &g_coord[(size_t)bq * 256 + h * 32];
    const float* __restrict__ aw = &g_attn[((size_t)bq * NH + h) * 16];

    float acc = 0.f;
    #pragma unroll
    for (int l = 0; l < 4; l++) {
        const int H = c_Hl[l], W = c_Wl[l];
        const float* __restrict__ vbase =
            &g_v[((size_t)(b * NV + c_start[l])) * 256 + h * 32 + lane];
        #pragma unroll
        for (int p = 0; p < 4; p++) {
            float x = coord[l * 8 + p * 2 + 0];
            float y = coord[l * 8 + p * 2 + 1];
            float w = aw[l * 4 + p];
            float x0f = floorf(x), y0f = floorf(y);
            int x0 = (int)x0f, y0 = (int)y0f;
            float wx1 = x - x0f, wy1 = y - y0f;
            float wx0 = 1.f - wx1, wy0 = 1.f - wy1;

            bool xin0 = (x0 >= 0) & (x0 < W);
            bool xin1 = (x0 >= -1) & (x0 < W - 1);
            bool yin0 = (y0 >= 0) & (y0 < H);
            bool yin1 = (y0 >= -1) & (y0 < H - 1);

            float v00 = 0.f, v01 = 0.f, v10 = 0.f, v11 = 0.f;
            if (yin0) {
                const float* rowp = vbase + (size_t)y0 * W * 256;
                if (xin0) v00 = rowp[(size_t)x0 * 256];
                if (xin1) v01 = rowp[(size_t)(x0 + 1) * 256];
            }
            if (yin1) {
                const float* rowp = vbase + (size_t)(y0 + 1) * W * 256;
                if (xin0) v10 = rowp[(size_t)x0 * 256];
                if (xin1) v11 = rowp[(size_t)(x0 + 1) * 256];
            }
            acc += w * (v00 * (wy0 * wx0) + v01 * (wy0 * wx1)
                      + v10 * (wy1 * wx0) + v11 * (wy1 * wx1));
        }
    }
    out[(size_t)bq * 256 + h * 32 + lane] = acc;
}

// ---------------------------------------------------------------------------
extern "C" void kernel_launch(void* const* d_in, const int* in_sizes, int n_in,
                              void* d_out, int out_size)
{
    const float* query = (const float*)d_in[0];
    const float* value = (const float*)d_in[1];
    const float* qpos  = (const float*)d_in[2];
    const float* refp  = (const float*)d_in[3];
    const float* Wval  = (const float*)d_in[4];
    const float* bval  = (const float*)d_in[5];
    const float* Woff  = (const float*)d_in[6];
    const float* boff  = (const float*)d_in[7];
    const float* Wattn = (const float*)d_in[8];
    const float* battn = (const float*)d_in[9];
    float* out = (float*)d_out;

    k_vproj<<<((VROWS + 63) / 64) * 2, 256>>>(value, Wval, bval);
    k_offattn<<<((NROWS + 63) / 64) * 3, 256>>>(query, qpos, refp, Woff, boff, Wattn, battn);
    k_sample<<<NROWS, 256>>>(out);
}

// round 10
// speedup vs baseline: 2.5890x; 1.2099x over previous
#include <cuda_runtime.h>
#include <cuda_fp16.h>
#include <cuda_bf16.h>
#include <cstdint>

#define BS 2
#define NQ 10000
#define NV 19560
#define EMBED 256
#define NH 8
#define HD 32
#define NROWS (BS*NQ)           // 20000
#define VROWS (BS*NV)           // 39120

__device__ __constant__ int c_Hl[4]    = {92, 46, 23, 12};
__device__ __constant__ int c_Wl[4]    = {160, 80, 40, 20};
__device__ __constant__ int c_start[4] = {0, 14720, 18400, 19320};

__device__ __half2 g_vh2[(size_t)VROWS * 128];     // projected value, fp16, [pos][h*16+dpair]
__device__ float g_coord[(size_t)NROWS * 256];
__device__ float g_attn[(size_t)NROWS * NH * 16];

#define PACK2(d, lo, hi) asm("mov.b64 %0, {%1, %2};" : "=l"(d) : "f"(lo), "f"(hi))
#define UNPACK2(lo, hi, d) asm("mov.b64 {%0, %1}, %2;" : "=f"(lo), "=f"(hi) : "l"(d))
#define FFMA2(c, a, b) asm("fma.rn.f32x2 %0, %1, %2, %0;" : "+l"(c) : "l"(a), "l"(b))

// ---------------------------------------------------------------------------
// Kernel B: value projection, register-tiled 8x4 per thread, k-chunk 16 with
// register-staged prefetch (LDG next chunk overlapped with compute).
// Epilogue converts to fp16 and writes g_vh2.
// ---------------------------------------------------------------------------
__global__ __launch_bounds__(256, 2)
void k_vproj(const float* __restrict__ value, const float* __restrict__ Wv,
             const float* __restrict__ bv)
{
    __shared__ float sA[16][68];     // [k][row]
    __shared__ float sW[16][132];    // [k][col]
    const int t = threadIdx.x;
    const int tx = t & 31, ty = t >> 5;
    const int row0 = (blockIdx.x >> 1) * 64;
    const int col0 = (blockIdx.x & 1) * 128;
    const int myrow = row0 + ty * 8;
    const int mycol = col0 + tx * 4;

    // fill-index assignment
    const int fa_k = t & 15;           // sA k
    const int fa_r = t >> 4;           // sA row base (0..15), rows +16*i
    const int fw_c = t & 127;          // sW col
    const int fw_k = t >> 7;           // sW k base (0/1), k = fw_k + 2*i

    float stA[4], stW[8];
    #pragma unroll
    for (int i = 0; i < 4; i++) {
        int row = row0 + fa_r + 16 * i;
        stA[i] = (row < VROWS) ? value[(size_t)row * 256 + fa_k] : 0.f;
    }
    #pragma unroll
    for (int i = 0; i < 8; i++)
        stW[i] = Wv[(size_t)(fw_k + 2 * i) * 256 + col0 + fw_c];
    #pragma unroll
    for (int i = 0; i < 4; i++) sA[fa_k][fa_r + 16 * i] = stA[i];
    #pragma unroll
    for (int i = 0; i < 8; i++) sW[fw_k + 2 * i][fw_c] = stW[i];
    __syncthreads();

    unsigned long long acc[16];
    #pragma unroll
    for (int c = 0; c < 4; c++) {
        float b = bv[mycol + c];
        unsigned long long b2; PACK2(b2, b, b);
        acc[c*4+0] = b2; acc[c*4+1] = b2; acc[c*4+2] = b2; acc[c*4+3] = b2;
    }

    for (int kc = 0; kc < 256; kc += 16) {
        const bool more = (kc + 16 < 256);
        if (more) {
            #pragma unroll
            for (int i = 0; i < 4; i++) {
                int row = row0 + fa_r + 16 * i;
                stA[i] = (row < VROWS) ? value[(size_t)row * 256 + kc + 16 + fa_k] : 0.f;
            }
            #pragma unroll
            for (int i = 0; i < 8; i++)
                stW[i] = Wv[(size_t)(kc + 16 + fw_k + 2 * i) * 256 + col0 + fw_c];
        }
        #pragma unroll
        for (int k = 0; k < 16; k++) {
            ulonglong2 a01 = *reinterpret_cast<const ulonglong2*>(&sA[k][ty*8]);
            ulonglong2 a23 = *reinterpret_cast<const ulonglong2*>(&sA[k][ty*8+4]);
            float4 w = *reinterpret_cast<const float4*>(&sW[k][tx*4]);
            unsigned long long w2[4];
            PACK2(w2[0], w.x, w.x); PACK2(w2[1], w.y, w.y);
            PACK2(w2[2], w.z, w.z); PACK2(w2[3], w.w, w.w);
            #pragma unroll
            for (int c = 0; c < 4; c++) {
                FFMA2(acc[c*4+0], a01.x, w2[c]);
                FFMA2(acc[c*4+1], a01.y, w2[c]);
                FFMA2(acc[c*4+2], a23.x, w2[c]);
                FFMA2(acc[c*4+3], a23.y, w2[c]);
            }
        }
        __syncthreads();
        if (more) {
            #pragma unroll
            for (int i = 0; i < 4; i++) sA[fa_k][fa_r + 16 * i] = stA[i];
            #pragma unroll
            for (int i = 0; i < 8; i++) sW[fw_k + 2 * i][fw_c] = stW[i];
        }
        __syncthreads();
    }

    #pragma unroll
    for (int rp = 0; rp < 4; rp++) {
        float o0[4], o1[4];
        #pragma unroll
        for (int c = 0; c < 4; c++) { UNPACK2(o0[c], o1[c], acc[c*4+rp]); }
        int row = myrow + rp * 2;
        if (row < VROWS) {
            __half2 ha = __floats2half2_rn(o0[0], o0[1]);
            __half2 hb = __floats2half2_rn(o0[2], o0[3]);
            uint2 u = make_uint2(*(unsigned*)&ha, *(unsigned*)&hb);
            *reinterpret_cast<uint2*>(&g_vh2[(size_t)row * 128 + (mycol >> 1)]) = u;
        }
        if (row + 1 < VROWS) {
            __half2 ha = __floats2half2_rn(o1[0], o1[1]);
            __half2 hb = __floats2half2_rn(o1[2], o1[3]);
            uint2 u = make_uint2(*(unsigned*)&ha, *(unsigned*)&hb);
            *reinterpret_cast<uint2*>(&g_vh2[(size_t)(row + 1) * 128 + (mycol >> 1)]) = u;
        }
    }
}

// ---------------------------------------------------------------------------
// Kernel A: fused offsets+attn GEMM, register-tiled, staged prefetch.
// Grid = 313 rowblks x 3 colblks; cb 0,1 = offsets, cb 2 = attn+softmax.
// ---------------------------------------------------------------------------
__global__ __launch_bounds__(256, 2)
void k_offattn(const float* __restrict__ query, const float* __restrict__ qpos,
               const float* __restrict__ refp,
               const float* __restrict__ Woff, const float* __restrict__ boff,
               const float* __restrict__ Wattn, const float* __restrict__ battn)
{
    __shared__ float sA[16][68];
    __shared__ float sW[16][132];
    const int t = threadIdx.x;
    const int tx = t & 31, ty = t >> 5;
    const int cb = blockIdx.x % 3;
    const int row0 = (blockIdx.x / 3) * 64;
    const int myrow = row0 + ty * 8;

    const bool is_attn = (cb == 2);
    const int col0 = is_attn ? 0 : cb * 128;
    const float* __restrict__ Wm = is_attn ? Wattn : Woff;
    const float* __restrict__ bm = is_attn ? battn : boff;
    const int ldw = is_attn ? 128 : 256;
    const int mycol = col0 + tx * 4;

    const int fa_k = t & 15;
    const int fa_r = t >> 4;
    const int fw_c = t & 127;
    const int fw_k = t >> 7;

    float stA[4], stW[8];
    #pragma unroll
    for (int i = 0; i < 4; i++) {
        int row = row0 + fa_r + 16 * i;
        float v = 0.f;
        if (row < NROWS) {
            size_t idx = (size_t)row * 256 + fa_k;
            v = query[idx] + qpos[idx];
        }
        stA[i] = v;
    }
    #pragma unroll
    for (int i = 0; i < 8; i++)
        stW[i] = Wm[(size_t)(fw_k + 2 * i) * ldw + col0 + fw_c];
    #pragma unroll
    for (int i = 0; i < 4; i++) sA[fa_k][fa_r + 16 * i] = stA[i];
    #pragma unroll
    for (int i = 0; i < 8; i++) sW[fw_k + 2 * i][fw_c] = stW[i];
    __syncthreads();

    unsigned long long acc[16];
    #pragma unroll
    for (int c = 0; c < 4; c++) {
        float b = bm[mycol + c];
        unsigned long long b2; PACK2(b2, b, b);
        acc[c*4+0] = b2; acc[c*4+1] = b2; acc[c*4+2] = b2; acc[c*4+3] = b2;
    }

    for (int kc = 0; kc < 256; kc += 16) {
        const bool more = (kc + 16 < 256);
        if (more) {
            #pragma unroll
            for (int i = 0; i < 4; i++) {
                int row = row0 + fa_r + 16 * i;
                float v = 0.f;
                if (row < NROWS) {
                    size_t idx = (size_t)row * 256 + kc + 16 + fa_k;
                    v = query[idx] + qpos[idx];
                }
                stA[i] = v;
            }
            #pragma unroll
            for (int i = 0; i < 8; i++)
                stW[i] = Wm[(size_t)(kc + 16 + fw_k + 2 * i) * ldw + col0 + fw_c];
        }
        #pragma unroll
        for (int k = 0; k < 16; k++) {
            ulonglong2 a01 = *reinterpret_cast<const ulonglong2*>(&sA[k][ty*8]);
            ulonglong2 a23 = *reinterpret_cast<const ulonglong2*>(&sA[k][ty*8+4]);
            float4 w = *reinterpret_cast<const float4*>(&sW[k][tx*4]);
            unsigned long long w2[4];
            PACK2(w2[0], w.x, w.x); PACK2(w2[1], w.y, w.y);
            PACK2(w2[2], w.z, w.z); PACK2(w2[3], w.w, w.w);
            #pragma unroll
            for (int c = 0; c < 4; c++) {
                FFMA2(acc[c*4+0], a01.x, w2[c]);
                FFMA2(acc[c*4+1], a01.y, w2[c]);
                FFMA2(acc[c*4+2], a23.x, w2[c]);
                FFMA2(acc[c*4+3], a23.y, w2[c]);
            }
        }
        __syncthreads();
        if (more) {
            #pragma unroll
            for (int i = 0; i < 4; i++) sA[fa_k][fa_r + 16 * i] = stA[i];
            #pragma unroll
            for (int i = 0; i < 8; i++) sW[fw_k + 2 * i][fw_c] = stW[i];
        }
        __syncthreads();
    }

    float o[8][4];
    #pragma unroll
    for (int rp = 0; rp < 4; rp++)
        #pragma unroll
        for (int c = 0; c < 4; c++)
            UNPACK2(o[rp*2][c], o[rp*2+1][c], acc[c*4+rp]);

    if (!is_attn) {
        #pragma unroll
        for (int c = 0; c < 4; c++) {
            int col = mycol + c;
            int cc = col & 1, p = (col >> 1) & 3, l = (col >> 3) & 3;
            float norm = (cc == 0) ? (float)c_Wl[l] : (float)c_Hl[l];
            #pragma unroll
            for (int r = 0; r < 8; r++) {
                int row = myrow + r;
                if (row < NROWS) {
                    float rv = refp[((size_t)row * 4 + p) * 2 + cc];
                    g_coord[(size_t)row * 256 + col] = rv * norm + o[r][c] - 0.5f;
                }
            }
        }
    } else {
        const int head = tx >> 2, sub = tx & 3;
        #pragma unroll
        for (int r = 0; r < 8; r++) {
            float m = fmaxf(fmaxf(o[r][0], o[r][1]), fmaxf(o[r][2], o[r][3]));
            m = fmaxf(m, __shfl_xor_sync(0xffffffffu, m, 1));
            m = fmaxf(m, __shfl_xor_sync(0xffffffffu, m, 2));
            float e[4], s = 0.f;
            #pragma unroll
            for (int c = 0; c < 4; c++) { e[c] = __expf(o[r][c] - m); s += e[c]; }
            s += __shfl_xor_sync(0xffffffffu, s, 1);
            s += __shfl_xor_sync(0xffffffffu, s, 2);
            float inv = 1.f / s;
            int row = myrow + r;
            if (row < NROWS) {
                #pragma unroll
                for (int c = 0; c < 4; c++)
                    g_attn[((size_t)row * NH + head) * 16 + sub * 4 + c] = e[c] * inv;
            }
        }
    }
}

// ---------------------------------------------------------------------------
// Kernel C: fp16 bilinear sampling. 2 bq per block (256 thr).
// Half-warp (16 lanes) per head; lane = channel pair (half2).
// ---------------------------------------------------------------------------
__global__ __launch_bounds__(256)
void k_sample(float* __restrict__ out)
{
    const int t = threadIdx.x;
    const int bq = blockIdx.x * 2 + (t >> 7);
    const int wt = t & 127;
    const int head = wt >> 4;            // 0..7
    const int dpair = wt & 15;           // channel pair 0..15
    const int b = bq / NQ;

    const float* __restrict__ coord = &g_coord[(size_t)bq * 256 + head * 32];
    const float* __restrict__ aw = &g_attn[((size_t)bq * NH + head) * 16];

    float accx = 0.f, accy = 0.f;
    #pragma unroll
    for (int l = 0; l < 4; l++) {
        const int H = c_Hl[l], W = c_Wl[l];
        const __half2* __restrict__ vbase =
            &g_vh2[((size_t)(b * NV + c_start[l])) * 128 + head * 16 + dpair];
        #pragma unroll
        for (int p = 0; p < 4; p++) {
            float x = coord[l * 8 + p * 2 + 0];
            float y = coord[l * 8 + p * 2 + 1];
            float w = aw[l * 4 + p];
            float x0f = floorf(x), y0f = floorf(y);
            int x0 = (int)x0f, y0 = (int)y0f;
            float wx1 = x - x0f, wy1 = y - y0f;
            float wx0 = 1.f - wx1, wy0 = 1.f - wy1;

            bool xin0 = (x0 >= 0) & (x0 < W);
            bool xin1 = (x0 >= -1) & (x0 < W - 1);
            bool yin0 = (y0 >= 0) & (y0 < H);
            bool yin1 = (y0 >= -1) & (y0 < H - 1);

            float2 v00 = {0.f,0.f}, v01 = {0.f,0.f}, v10 = {0.f,0.f}, v11 = {0.f,0.f};
            if (yin0) {
                const __half2* rowp = vbase + (size_t)y0 * W * 128;
                if (xin0) v00 = __half22float2(rowp[(size_t)x0 * 128]);
                if (xin1) v01 = __half22float2(rowp[(size_t)(x0 + 1) * 128]);
            }
            if (yin1) {
                const __half2* rowp = vbase + (size_t)(y0 + 1) * W * 128;
                if (xin0) v10 = __half22float2(rowp[(size_t)x0 * 128]);
                if (xin1) v11 = __half22float2(rowp[(size_t)(x0 + 1) * 128]);
            }
            float w00 = wy0 * wx0, w01 = wy0 * wx1, w10 = wy1 * wx0, w11 = wy1 * wx1;
            accx += w * (v00.x * w00 + v01.x * w01 + v10.x * w10 + v11.x * w11);
            accy += w * (v00.y * w00 + v01.y * w01 + v10.y * w10 + v11.y * w11);
        }
    }
    *reinterpret_cast<float2*>(&out[(size_t)bq * 256 + head * 32 + dpair * 2]) =
        make_float2(accx, accy);
}

// ---------------------------------------------------------------------------
extern "C" void kernel_launch(void* const* d_in, const int* in_sizes, int n_in,
                              void* d_out, int out_size)
{
    const float* query = (const float*)d_in[0];
    const float* value = (const float*)d_in[1];
    const float* qpos  = (const float*)d_in[2];
    const float* refp  = (const float*)d_in[3];
    const float* Wval  = (const float*)d_in[4];
    const float* bval  = (const float*)d_in[5];
    const float* Woff  = (const float*)d_in[6];
    const float* boff  = (const float*)d_in[7];
    const float* Wattn = (const float*)d_in[8];
    const float* battn = (const float*)d_in[9];
    float* out = (float*)d_out;

    k_vproj<<<((VROWS + 63) / 64) * 2, 256>>>(value, Wval, bval);
    k_offattn<<<((NROWS + 63) / 64) * 3, 256>>>(query, qpos, refp, Woff, boff, Wattn, battn);
    k_sample<<<NROWS / 2, 256>>>(out);
}

// round 12
// speedup vs baseline: 3.1656x; 1.2227x over previous
#include <cuda_runtime.h>
#include <cuda_fp16.h>
#include <cstdint>

#define BS 2
#define NQ 10000
#define NV 19560
#define NROWS (BS*NQ)           // 20000
#define VROWS (BS*NV)           // 39120
#define NH 8

__device__ __constant__ int c_Hl[4]    = {92, 46, 23, 12};
__device__ __constant__ int c_Wl[4]    = {160, 80, 40, 20};
__device__ __constant__ int c_start[4] = {0, 14720, 18400, 19320};

__device__ __half2 g_vh2[(size_t)VROWS * 128];   // projected value fp16
__device__ float g_coord[(size_t)NROWS * 256];
__device__ float g_attn[(size_t)NROWS * NH * 16];
__device__ __half g_wtv[256 * 256];              // W_val^T  [n][k]
__device__ __half g_wt[384 * 256];               // [W_off^T ; W_attn^T]  [n][k]

__device__ __forceinline__ uint32_t sm32(const void* p) {
    return (uint32_t)__cvta_generic_to_shared(p);
}
__device__ __forceinline__ uint32_t h2u(__half2 h) { return *reinterpret_cast<uint32_t*>(&h); }
__device__ __forceinline__ void ldsm4(uint32_t* r, uint32_t a) {
    asm volatile("ldmatrix.sync.aligned.m8n8.x4.shared.b16 {%0,%1,%2,%3}, [%4];"
        : "=r"(r[0]), "=r"(r[1]), "=r"(r[2]), "=r"(r[3]) : "r"(a));
}
__device__ __forceinline__ void mma16816(float* d, const uint32_t* a, uint32_t b0, uint32_t b1) {
    asm volatile("mma.sync.aligned.m16n8k16.row.col.f32.f16.f16.f32 "
        "{%0,%1,%2,%3},{%4,%5,%6,%7},{%8,%9},{%0,%1,%2,%3};"
        : "+f"(d[0]), "+f"(d[1]), "+f"(d[2]), "+f"(d[3])
        : "r"(a[0]), "r"(a[1]), "r"(a[2]), "r"(a[3]), "r"(b0), "r"(b1));
}

// ---------------------------------------------------------------------------
// Prep: transpose+convert W_val (256x256), W_off (256x256), W_attn (256x128)
// into fp16 [n][k] globals. 160 blocks of 256 threads, 32x32 smem tiles.
// ---------------------------------------------------------------------------
__global__ __launch_bounds__(256)
void k_prep(const float* __restrict__ Wv, const float* __restrict__ Wo,
            const float* __restrict__ Wa)
{
    __shared__ float tile[32][33];
    int bid = blockIdx.x;
    const float* src; __half* dst; int srcld, tk, tn;
    if (bid < 64)       { src = Wv; dst = g_wtv;           srcld = 256; tk = bid >> 3; tn = bid & 7; }
    else if (bid < 128) { bid -= 64;  src = Wo; dst = g_wt; srcld = 256; tk = bid >> 3; tn = bid & 7; }
    else                { bid -= 128; src = Wa; dst = g_wt + 256 * 256; srcld = 128; tk = bid >> 2; tn = bid & 3; }
    int tx = threadIdx.x & 31, ty = threadIdx.x >> 5;
    #pragma unroll
    for (int i = 0; i < 4; i++)
        tile[ty + i * 8][tx] = src[(size_t)(tk * 32 + ty + i * 8) * srcld + tn * 32 + tx];
    __syncthreads();
    #pragma unroll
    for (int i = 0; i < 4; i++)
        dst[(size_t)(tn * 32 + ty + i * 8) * 256 + tk * 32 + tx] = __float2half(tile[tx][ty + i * 8]);
}

// ---------------------------------------------------------------------------
// Tensor-core GEMM skeleton: block 128(M) x 64(N), 8 warps (4x2), warp 32x32.
// sA [128][72] halves, sB [64][72] halves. k-chunks of 64, mma k16.
// ---------------------------------------------------------------------------
#define SA_STR 72
#define SB_STR 72

// ---------------------------------------------------------------------------
// Kernel B: value projection -> g_vh2 (fp16)
// ---------------------------------------------------------------------------
__global__ __launch_bounds__(256)
void k_vproj(const float* __restrict__ value, const float* __restrict__ bv)
{
    __shared__ __half sA[128][SA_STR];
    __shared__ __half sB[64][SB_STR];
    const int t = threadIdx.x;
    const int lane = t & 31, wid = t >> 5;
    const int wm = wid & 3, wn = wid >> 2;
    const int row0 = (blockIdx.x >> 2) * 128;
    const int col0 = (blockIdx.x & 3) * 64;
    const int g = lane >> 2, tig = lane & 3;

    float d[2][4][4];
    #pragma unroll
    for (int nt = 0; nt < 4; nt++) {
        float b0v = bv[col0 + wn * 32 + nt * 8 + 2 * tig];
        float b1v = bv[col0 + wn * 32 + nt * 8 + 2 * tig + 1];
        #pragma unroll
        for (int mt = 0; mt < 2; mt++) {
            d[mt][nt][0] = b0v; d[mt][nt][1] = b1v;
            d[mt][nt][2] = b0v; d[mt][nt][3] = b1v;
        }
    }

    const int fr = t >> 1, fseg = (t & 1) * 32;      // sA fill: row, 32-half seg
    const int fn = t >> 2, fbs = (t & 3) * 16;       // sB fill: n-row, 16-half seg

    for (int kc = 0; kc < 256; kc += 64) {
        // fill sA (fp32 value -> fp16)
        {
            int grow = row0 + fr;
            uint32_t hw[16];
            if (grow < VROWS) {
                const float4* src = reinterpret_cast<const float4*>(
                    &value[(size_t)grow * 256 + kc + fseg]);
                #pragma unroll
                for (int i = 0; i < 8; i++) {
                    float4 v = src[i];
                    hw[2 * i]     = h2u(__floats2half2_rn(v.x, v.y));
                    hw[2 * i + 1] = h2u(__floats2half2_rn(v.z, v.w));
                }
            } else {
                #pragma unroll
                for (int i = 0; i < 16; i++) hw[i] = 0u;
            }
            uint4* dst = reinterpret_cast<uint4*>(&sA[fr][fseg]);
            #pragma unroll
            for (int j = 0; j < 4; j++)
                dst[j] = make_uint4(hw[4*j], hw[4*j+1], hw[4*j+2], hw[4*j+3]);
        }
        // fill sB (fp16 W^T)
        {
            const uint4* wsrc = reinterpret_cast<const uint4*>(
                &g_wtv[(size_t)(col0 + fn) * 256 + kc + fbs]);
            uint4* dst = reinterpret_cast<uint4*>(&sB[fn][fbs]);
            dst[0] = wsrc[0]; dst[1] = wsrc[1];
        }
        __syncthreads();

        #pragma unroll
        for (int k0 = 0; k0 < 64; k0 += 16) {
            uint32_t a[2][4], b[2][4];
            #pragma unroll
            for (int mt = 0; mt < 2; mt++)
                ldsm4(a[mt], sm32(&sA[wm * 32 + mt * 16 + (lane & 15)][k0 + (lane >> 4) * 8]));
            #pragma unroll
            for (int np = 0; np < 2; np++)
                ldsm4(b[np], sm32(&sB[wn * 32 + np * 16 + (lane & 7) + ((lane >> 4) << 3)]
                                     [k0 + ((lane >> 3) & 1) * 8]));
            #pragma unroll
            for (int mt = 0; mt < 2; mt++)
                #pragma unroll
                for (int nt = 0; nt < 4; nt++)
                    mma16816(d[mt][nt], a[mt], b[nt >> 1][(nt & 1) * 2], b[nt >> 1][(nt & 1) * 2 + 1]);
        }
        __syncthreads();
    }

    #pragma unroll
    for (int mt = 0; mt < 2; mt++)
        #pragma unroll
        for (int nt = 0; nt < 4; nt++) {
            int colp = (col0 + wn * 32 + nt * 8 + 2 * tig) >> 1;
            int rA = row0 + wm * 32 + mt * 16 + g;
            int rB = rA + 8;
            if (rA < VROWS)
                g_vh2[(size_t)rA * 128 + colp] = __floats2half2_rn(d[mt][nt][0], d[mt][nt][1]);
            if (rB < VROWS)
                g_vh2[(size_t)rB * 128 + colp] = __floats2half2_rn(d[mt][nt][2], d[mt][nt][3]);
        }
}

// ---------------------------------------------------------------------------
// Kernel A: q=query+qpos; [off|attn] GEMM on tensor cores. Grid = 157 x 6.
// cb 0..3 -> offset cols (coord epilogue), cb 4..5 -> attn cols (softmax).
// ---------------------------------------------------------------------------
__global__ __launch_bounds__(256)
void k_offattn(const float* __restrict__ query, const float* __restrict__ qpos,
               const float* __restrict__ refp,
               const float* __restrict__ boff, const float* __restrict__ battn)
{
    __shared__ __half sA[128][SA_STR];
    __shared__ __half sB[64][SB_STR];
    const int t = threadIdx.x;
    const int lane = t & 31, wid = t >> 5;
    const int wm = wid & 3, wn = wid >> 2;
    const int cb = blockIdx.x % 6;
    const int row0 = (blockIdx.x / 6) * 128;
    const int g = lane >> 2, tig = lane & 3;
    const bool is_attn = (cb >= 4);

    float d[2][4][4];
    #pragma unroll
    for (int nt = 0; nt < 4; nt++) {
        int col = cb * 64 + wn * 32 + nt * 8 + 2 * tig;
        float b0v = is_attn ? battn[col - 256] : boff[col];
        float b1v = is_attn ? battn[col - 255] : boff[col + 1];
        #pragma unroll
        for (int mt = 0; mt < 2; mt++) {
            d[mt][nt][0] = b0v; d[mt][nt][1] = b1v;
            d[mt][nt][2] = b0v; d[mt][nt][3] = b1v;
        }
    }

    const int fr = t >> 1, fseg = (t & 1) * 32;
    const int fn = t >> 2, fbs = (t & 3) * 16;

    for (int kc = 0; kc < 256; kc += 64) {
        {
            int grow = row0 + fr;
            uint32_t hw[16];
            if (grow < NROWS) {
                const float4* s1 = reinterpret_cast<const float4*>(
                    &query[(size_t)grow * 256 + kc + fseg]);
                const float4* s2 = reinterpret_cast<const float4*>(
                    &qpos[(size_t)grow * 256 + kc + fseg]);
                #pragma unroll
                for (int i = 0; i < 8; i++) {
                    float4 v = s1[i], u = s2[i];
                    hw[2 * i]     = h2u(__floats2half2_rn(v.x + u.x, v.y + u.y));
                    hw[2 * i + 1] = h2u(__floats2half2_rn(v.z + u.z, v.w + u.w));
                }
            } else {
                #pragma unroll
                for (int i = 0; i < 16; i++) hw[i] = 0u;
            }
            uint4* dst = reinterpret_cast<uint4*>(&sA[fr][fseg]);
            #pragma unroll
            for (int j = 0; j < 4; j++)
                dst[j] = make_uint4(hw[4*j], hw[4*j+1], hw[4*j+2], hw[4*j+3]);
        }
        {
            const uint4* wsrc = reinterpret_cast<const uint4*>(
                &g_wt[(size_t)(cb * 64 + fn) * 256 + kc + fbs]);
            uint4* dst = reinterpret_cast<uint4*>(&sB[fn][fbs]);
            dst[0] = wsrc[0]; dst[1] = wsrc[1];
        }
        __syncthreads();

        #pragma unroll
        for (int k0 = 0; k0 < 64; k0 += 16) {
            uint32_t a[2][4], b[2][4];
            #pragma unroll
            for (int mt = 0; mt < 2; mt++)
                ldsm4(a[mt], sm32(&sA[wm * 32 + mt * 16 + (lane & 15)][k0 + (lane >> 4) * 8]));
            #pragma unroll
            for (int np = 0; np < 2; np++)
                ldsm4(b[np], sm32(&sB[wn * 32 + np * 16 + (lane & 7) + ((lane >> 4) << 3)]
                                     [k0 + ((lane >> 3) & 1) * 8]));
            #pragma unroll
            for (int mt = 0; mt < 2; mt++)
                #pragma unroll
                for (int nt = 0; nt < 4; nt++)
                    mma16816(d[mt][nt], a[mt], b[nt >> 1][(nt & 1) * 2], b[nt >> 1][(nt & 1) * 2 + 1]);
        }
        __syncthreads();
    }

    if (!is_attn) {
        // coord epilogue: col = cb*64 + wn*32 + nt*8 + 2tig + {0,1}
        #pragma unroll
        for (int nt = 0; nt < 4; nt++) {
            #pragma unroll
            for (int cp = 0; cp < 2; cp++) {
                int col = cb * 64 + wn * 32 + nt * 8 + 2 * tig + cp;
                int cc = col & 1, p = (col >> 1) & 3, l = (col >> 3) & 3;
                float norm = (cc == 0) ? (float)c_Wl[l] : (float)c_Hl[l];
                #pragma unroll
                for (int mt = 0; mt < 2; mt++) {
                    int rA = row0 + wm * 32 + mt * 16 + g;
                    int rB = rA + 8;
                    if (rA < NROWS) {
                        float rv = refp[(size_t)rA * 8 + p * 2 + cc];
                        g_coord[(size_t)rA * 256 + col] = rv * norm + d[mt][nt][cp] - 0.5f;
                    }
                    if (rB < NROWS) {
                        float rv = refp[(size_t)rB * 8 + p * 2 + cc];
                        g_coord[(size_t)rB * 256 + col] = rv * norm + d[mt][nt][2 + cp] - 0.5f;
                    }
                }
            }
        }
    } else {
        // softmax epilogue: warp covers 2 heads (32 attn cols)
        #pragma unroll
        for (int hh = 0; hh < 2; hh++) {
            int head = (cb - 4) * 4 + wn * 2 + hh;
            #pragma unroll
            for (int mt = 0; mt < 2; mt++) {
                #pragma unroll
                for (int lohi = 0; lohi < 2; lohi++) {
                    float v0 = d[mt][2 * hh][lohi * 2];
                    float v1 = d[mt][2 * hh][lohi * 2 + 1];
                    float v2 = d[mt][2 * hh + 1][lohi * 2];
                    float v3 = d[mt][2 * hh + 1][lohi * 2 + 1];
                    float m = fmaxf(fmaxf(v0, v1), fmaxf(v2, v3));
                    m = fmaxf(m, __shfl_xor_sync(0xffffffffu, m, 1));
                    m = fmaxf(m, __shfl_xor_sync(0xffffffffu, m, 2));
                    float e0 = __expf(v0 - m), e1 = __expf(v1 - m);
                    float e2 = __expf(v2 - m), e3 = __expf(v3 - m);
                    float s = e0 + e1 + e2 + e3;
                    s += __shfl_xor_sync(0xffffffffu, s, 1);
                    s += __shfl_xor_sync(0xffffffffu, s, 2);
                    float inv = 1.f / s;
                    int row = row0 + wm * 32 + mt * 16 + g + lohi * 8;
                    if (row < NROWS) {
                        float* ap = &g_attn[((size_t)row * NH + head) * 16];
                        ap[2 * tig]     = e0 * inv;
                        ap[2 * tig + 1] = e1 * inv;
                        ap[8 + 2 * tig]     = e2 * inv;
                        ap[8 + 2 * tig + 1] = e3 * inv;
                    }
                }
            }
        }
    }
}

// ---------------------------------------------------------------------------
// Kernel C: fp16 bilinear sampling (unchanged from R10).
// ---------------------------------------------------------------------------
__global__ __launch_bounds__(256)
void k_sample(float* __restrict__ out)
{
    const int t = threadIdx.x;
    const int bq = blockIdx.x * 2 + (t >> 7);
    const int wt = t & 127;
    const int head = wt >> 4;
    const int dpair = wt & 15;
    const int b = bq / NQ;

    const float* __restrict__ coord = &g_coord[(size_t)bq * 256 + head * 32];
    const float* __restrict__ aw = &g_attn[((size_t)bq * NH + head) * 16];

    float accx = 0.f, accy = 0.f;
    #pragma unroll
    for (int l = 0; l < 4; l++) {
        const int H = c_Hl[l], W = c_Wl[l];
        const __half2* __restrict__ vbase =
            &g_vh2[((size_t)(b * NV + c_start[l])) * 128 + head * 16 + dpair];
        #pragma unroll
        for (int p = 0; p < 4; p++) {
            float x = coord[l * 8 + p * 2 + 0];
            float y = coord[l * 8 + p * 2 + 1];
            float w = aw[l * 4 + p];
            float x0f = floorf(x), y0f = floorf(y);
            int x0 = (int)x0f, y0 = (int)y0f;
            float wx1 = x - x0f, wy1 = y - y0f;
            float wx0 = 1.f - wx1, wy0 = 1.f - wy1;

            bool xin0 = (x0 >= 0) & (x0 < W);
            bool xin1 = (x0 >= -1) & (x0 < W - 1);
            bool yin0 = (y0 >= 0) & (y0 < H);
            bool yin1 = (y0 >= -1) & (y0 < H - 1);

            float2 v00 = {0.f,0.f}, v01 = {0.f,0.f}, v10 = {0.f,0.f}, v11 = {0.f,0.f};
            if (yin0) {
                const __half2* rowp = vbase + (size_t)y0 * W * 128;
                if (xin0) v00 = __half22float2(rowp[(size_t)x0 * 128]);
                if (xin1) v01 = __half22float2(rowp[(size_t)(x0 + 1) * 128]);
            }
            if (yin1) {
                const __half2* rowp = vbase + (size_t)(y0 + 1) * W * 128;
                if (xin0) v10 = __half22float2(rowp[(size_t)x0 * 128]);
                if (xin1) v11 = __half22float2(rowp[(size_t)(x0 + 1) * 128]);
            }
            float w00 = wy0 * wx0, w01 = wy0 * wx1, w10 = wy1 * wx0, w11 = wy1 * wx1;
            accx += w * (v00.x * w00 + v01.x * w01 + v10.x * w10 + v11.x * w11);
            accy += w * (v00.y * w00 + v01.y * w01 + v10.y * w10 + v11.y * w11);
        }
    }
    *reinterpret_cast<float2*>(&out[(size_t)bq * 256 + head * 32 + dpair * 2]) =
        make_float2(accx, accy);
}

// ---------------------------------------------------------------------------
extern "C" void kernel_launch(void* const* d_in, const int* in_sizes, int n_in,
                              void* d_out, int out_size)
{
    const float* query = (const float*)d_in[0];
    const float* value = (const float*)d_in[1];
    const float* qpos  = (const float*)d_in[2];
    const float* refp  = (const float*)d_in[3];
    const float* Wval  = (const float*)d_in[4];
    const float* bval  = (const float*)d_in[5];
    const float* Woff  = (const float*)d_in[6];
    const float* boff  = (const float*)d_in[7];
    const float* Wattn = (const float*)d_in[8];
    const float* battn = (const float*)d_in[9];
    float* out = (float*)d_out;

    k_prep<<<160, 256>>>(Wval, Woff, Wattn);
    k_vproj<<<((VROWS + 127) / 128) * 4, 256>>>(value, bval);
    k_offattn<<<((NROWS + 127) / 128) * 6, 256>>>(query, qpos, refp, boff, battn);
    k_sample<<<NROWS / 2, 256>>>(out);
}

// round 13
// speedup vs baseline: 3.7353x; 1.1800x over previous
#include <cuda_runtime.h>
#include <cuda_fp16.h>
#include <cstdint>

#define BS 2
#define NQ 10000
#define NV 19560
#define NROWS (BS*NQ)           // 20000
#define VROWS (BS*NV)           // 39120
#define NH 8

__device__ __constant__ int c_Hl[4]    = {92, 46, 23, 12};
__device__ __constant__ int c_Wl[4]    = {160, 80, 40, 20};
__device__ __constant__ int c_start[4] = {0, 14720, 18400, 19320};

__device__ __half2 g_vh2[(size_t)VROWS * 128];   // projected value fp16
__device__ float g_coord[(size_t)NROWS * 256];
__device__ float g_attn[(size_t)NROWS * NH * 16];
__device__ __half g_wtv[256 * 256];              // W_val^T  [n][k]
__device__ __half g_wt[384 * 256];               // [W_off^T ; W_attn^T]  [n][k]

#define PACK2(d, lo, hi) asm("mov.b64 %0, {%1, %2};" : "=l"(d) : "f"(lo), "f"(hi))
#define UNPACK2(lo, hi, d) asm("mov.b64 {%0, %1}, %2;" : "=f"(lo), "=f"(hi) : "l"(d))
#define FFMA2(c, a, b) asm("fma.rn.f32x2 %0, %1, %2, %0;" : "+l"(c) : "l"(a), "l"(b))

__device__ __forceinline__ uint32_t sm32(const void* p) {
    return (uint32_t)__cvta_generic_to_shared(p);
}
__device__ __forceinline__ uint32_t h2u(__half2 h) { return *reinterpret_cast<uint32_t*>(&h); }
__device__ __forceinline__ void ldsm4(uint32_t* r, uint32_t a) {
    asm volatile("ldmatrix.sync.aligned.m8n8.x4.shared.b16 {%0,%1,%2,%3}, [%4];"
        : "=r"(r[0]), "=r"(r[1]), "=r"(r[2]), "=r"(r[3]) : "r"(a));
}
__device__ __forceinline__ void mma16816(float* d, const uint32_t* a, uint32_t b0, uint32_t b1) {
    asm volatile("mma.sync.aligned.m16n8k16.row.col.f32.f16.f16.f32 "
        "{%0,%1,%2,%3},{%4,%5,%6,%7},{%8,%9},{%0,%1,%2,%3};"
        : "+f"(d[0]), "+f"(d[1]), "+f"(d[2]), "+f"(d[3])
        : "r"(a[0]), "r"(a[1]), "r"(a[2]), "r"(a[3]), "r"(b0), "r"(b1));
}

// ---------------------------------------------------------------------------
// Prep: transpose+convert weights to fp16 [n][k]. 160 blocks x 256 thr.
// ---------------------------------------------------------------------------
__global__ __launch_bounds__(256)
void k_prep(const float* __restrict__ Wv, const float* __restrict__ Wo,
            const float* __restrict__ Wa)
{
    __shared__ float tile[32][33];
    int bid = blockIdx.x;
    const float* src; __half* dst; int srcld, tk, tn;
    if (bid < 64)       { src = Wv; dst = g_wtv;           srcld = 256; tk = bid >> 3; tn = bid & 7; }
    else if (bid < 128) { bid -= 64;  src = Wo; dst = g_wt; srcld = 256; tk = bid >> 3; tn = bid & 7; }
    else                { bid -= 128; src = Wa; dst = g_wt + 256 * 256; srcld = 128; tk = bid >> 2; tn = bid & 3; }
    int tx = threadIdx.x & 31, ty = threadIdx.x >> 5;
    #pragma unroll
    for (int i = 0; i < 4; i++)
        tile[ty + i * 8][tx] = src[(size_t)(tk * 32 + ty + i * 8) * srcld + tn * 32 + tx];
    __syncthreads();
    #pragma unroll
    for (int i = 0; i < 4; i++)
        dst[(size_t)(tn * 32 + ty + i * 8) * 256 + tk * 32 + tx] = __float2half(tile[tx][ty + i * 8]);
}

#define SA_STR 72
#define SB_STR 72

// ---------------------------------------------------------------------------
// Kernel B: value projection -> g_vh2 (fp16). Tensor-core 128x64 blocks.
// ---------------------------------------------------------------------------
__global__ __launch_bounds__(256)
void k_vproj(const float* __restrict__ value, const float* __restrict__ bv)
{
    __shared__ __half sA[128][SA_STR];
    __shared__ __half sB[64][SB_STR];
    const int t = threadIdx.x;
    const int lane = t & 31, wid = t >> 5;
    const int wm = wid & 3, wn = wid >> 2;
    const int row0 = (blockIdx.x >> 2) * 128;
    const int col0 = (blockIdx.x & 3) * 64;
    const int g = lane >> 2, tig = lane & 3;

    float d[2][4][4];
    #pragma unroll
    for (int nt = 0; nt < 4; nt++) {
        float b0v = bv[col0 + wn * 32 + nt * 8 + 2 * tig];
        float b1v = bv[col0 + wn * 32 + nt * 8 + 2 * tig + 1];
        #pragma unroll
        for (int mt = 0; mt < 2; mt++) {
            d[mt][nt][0] = b0v; d[mt][nt][1] = b1v;
            d[mt][nt][2] = b0v; d[mt][nt][3] = b1v;
        }
    }

    const int fr = t >> 1, fseg = (t & 1) * 32;
    const int fn = t >> 2, fbs = (t & 3) * 16;

    for (int kc = 0; kc < 256; kc += 64) {
        {
            int grow = row0 + fr;
            uint32_t hw[16];
            if (grow < VROWS) {
                const float4* src = reinterpret_cast<const float4*>(
                    &value[(size_t)grow * 256 + kc + fseg]);
                #pragma unroll
                for (int i = 0; i < 8; i++) {
                    float4 v = src[i];
                    hw[2 * i]     = h2u(__floats2half2_rn(v.x, v.y));
                    hw[2 * i + 1] = h2u(__floats2half2_rn(v.z, v.w));
                }
            } else {
                #pragma unroll
                for (int i = 0; i < 16; i++) hw[i] = 0u;
            }
            uint4* dst = reinterpret_cast<uint4*>(&sA[fr][fseg]);
            #pragma unroll
            for (int j = 0; j < 4; j++)
                dst[j] = make_uint4(hw[4*j], hw[4*j+1], hw[4*j+2], hw[4*j+3]);
        }
        {
            const uint4* wsrc = reinterpret_cast<const uint4*>(
                &g_wtv[(size_t)(col0 + fn) * 256 + kc + fbs]);
            uint4* dst = reinterpret_cast<uint4*>(&sB[fn][fbs]);
            dst[0] = wsrc[0]; dst[1] = wsrc[1];
        }
        __syncthreads();

        #pragma unroll
        for (int k0 = 0; k0 < 64; k0 += 16) {
            uint32_t a[2][4], b[2][4];
            #pragma unroll
            for (int mt = 0; mt < 2; mt++)
                ldsm4(a[mt], sm32(&sA[wm * 32 + mt * 16 + (lane & 15)][k0 + (lane >> 4) * 8]));
            #pragma unroll
            for (int np = 0; np < 2; np++)
                ldsm4(b[np], sm32(&sB[wn * 32 + np * 16 + (lane & 7) + ((lane >> 4) << 3)]
                                     [k0 + ((lane >> 3) & 1) * 8]));
            #pragma unroll
            for (int mt = 0; mt < 2; mt++)
                #pragma unroll
                for (int nt = 0; nt < 4; nt++)
                    mma16816(d[mt][nt], a[mt], b[nt >> 1][(nt & 1) * 2], b[nt >> 1][(nt & 1) * 2 + 1]);
        }
        __syncthreads();
    }

    #pragma unroll
    for (int mt = 0; mt < 2; mt++)
        #pragma unroll
        for (int nt = 0; nt < 4; nt++) {
            int colp = (col0 + wn * 32 + nt * 8 + 2 * tig) >> 1;
            int rA = row0 + wm * 32 + mt * 16 + g;
            int rB = rA + 8;
            if (rA < VROWS)
                g_vh2[(size_t)rA * 128 + colp] = __floats2half2_rn(d[mt][nt][0], d[mt][nt][1]);
            if (rB < VROWS)
                g_vh2[(size_t)rB * 128 + colp] = __floats2half2_rn(d[mt][nt][2], d[mt][nt][3]);
        }
}

// ---------------------------------------------------------------------------
// Kernel A: q=query+qpos; [off|attn] GEMM on tensor cores. Grid = 157 x 6.
// ---------------------------------------------------------------------------
__global__ __launch_bounds__(256)
void k_offattn(const float* __restrict__ query, const float* __restrict__ qpos,
               const float* __restrict__ refp,
               const float* __restrict__ boff, const float* __restrict__ battn)
{
    __shared__ __half sA[128][SA_STR];
    __shared__ __half sB[64][SB_STR];
    const int t = threadIdx.x;
    const int lane = t & 31, wid = t >> 5;
    const int wm = wid & 3, wn = wid >> 2;
    const int cb = blockIdx.x % 6;
    const int row0 = (blockIdx.x / 6) * 128;
    const int g = lane >> 2, tig = lane & 3;
    const bool is_attn = (cb >= 4);

    float d[2][4][4];
    #pragma unroll
    for (int nt = 0; nt < 4; nt++) {
        int col = cb * 64 + wn * 32 + nt * 8 + 2 * tig;
        float b0v = is_attn ? battn[col - 256] : boff[col];
        float b1v = is_attn ? battn[col - 255] : boff[col + 1];
        #pragma unroll
        for (int mt = 0; mt < 2; mt++) {
            d[mt][nt][0] = b0v; d[mt][nt][1] = b1v;
            d[mt][nt][2] = b0v; d[mt][nt][3] = b1v;
        }
    }

    const int fr = t >> 1, fseg = (t & 1) * 32;
    const int fn = t >> 2, fbs = (t & 3) * 16;

    for (int kc = 0; kc < 256; kc += 64) {
        {
            int grow = row0 + fr;
            uint32_t hw[16];
            if (grow < NROWS) {
                const float4* s1 = reinterpret_cast<const float4*>(
                    &query[(size_t)grow * 256 + kc + fseg]);
                const float4* s2 = reinterpret_cast<const float4*>(
                    &qpos[(size_t)grow * 256 + kc + fseg]);
                #pragma unroll
                for (int i = 0; i < 8; i++) {
                    float4 v = s1[i], u = s2[i];
                    hw[2 * i]     = h2u(__floats2half2_rn(v.x + u.x, v.y + u.y));
                    hw[2 * i + 1] = h2u(__floats2half2_rn(v.z + u.z, v.w + u.w));
                }
            } else {
                #pragma unroll
                for (int i = 0; i < 16; i++) hw[i] = 0u;
            }
            uint4* dst = reinterpret_cast<uint4*>(&sA[fr][fseg]);
            #pragma unroll
            for (int j = 0; j < 4; j++)
                dst[j] = make_uint4(hw[4*j], hw[4*j+1], hw[4*j+2], hw[4*j+3]);
        }
        {
            const uint4* wsrc = reinterpret_cast<const uint4*>(
                &g_wt[(size_t)(cb * 64 + fn) * 256 + kc + fbs]);
            uint4* dst = reinterpret_cast<uint4*>(&sB[fn][fbs]);
            dst[0] = wsrc[0]; dst[1] = wsrc[1];
        }
        __syncthreads();

        #pragma unroll
        for (int k0 = 0; k0 < 64; k0 += 16) {
            uint32_t a[2][4], b[2][4];
            #pragma unroll
            for (int mt = 0; mt < 2; mt++)
                ldsm4(a[mt], sm32(&sA[wm * 32 + mt * 16 + (lane & 15)][k0 + (lane >> 4) * 8]));
            #pragma unroll
            for (int np = 0; np < 2; np++)
                ldsm4(b[np], sm32(&sB[wn * 32 + np * 16 + (lane & 7) + ((lane >> 4) << 3)]
                                     [k0 + ((lane >> 3) & 1) * 8]));
            #pragma unroll
            for (int mt = 0; mt < 2; mt++)
                #pragma unroll
                for (int nt = 0; nt < 4; nt++)
                    mma16816(d[mt][nt], a[mt], b[nt >> 1][(nt & 1) * 2], b[nt >> 1][(nt & 1) * 2 + 1]);
        }
        __syncthreads();
    }

    if (!is_attn) {
        #pragma unroll
        for (int nt = 0; nt < 4; nt++) {
            #pragma unroll
            for (int cp = 0; cp < 2; cp++) {
                int col = cb * 64 + wn * 32 + nt * 8 + 2 * tig + cp;
                int cc = col & 1, p = (col >> 1) & 3, l = (col >> 3) & 3;
                float norm = (cc == 0) ? (float)c_Wl[l] : (float)c_Hl[l];
                #pragma unroll
                for (int mt = 0; mt < 2; mt++) {
                    int rA = row0 + wm * 32 + mt * 16 + g;
                    int rB = rA + 8;
                    if (rA < NROWS) {
                        float rv = refp[(size_t)rA * 8 + p * 2 + cc];
                        g_coord[(size_t)rA * 256 + col] = rv * norm + d[mt][nt][cp] - 0.5f;
                    }
                    if (rB < NROWS) {
                        float rv = refp[(size_t)rB * 8 + p * 2 + cc];
                        g_coord[(size_t)rB * 256 + col] = rv * norm + d[mt][nt][2 + cp] - 0.5f;
                    }
                }
            }
        }
    } else {
        #pragma unroll
        for (int hh = 0; hh < 2; hh++) {
            int head = (cb - 4) * 4 + wn * 2 + hh;
            #pragma unroll
            for (int mt = 0; mt < 2; mt++) {
                #pragma unroll
                for (int lohi = 0; lohi < 2; lohi++) {
                    float v0 = d[mt][2 * hh][lohi * 2];
                    float v1 = d[mt][2 * hh][lohi * 2 + 1];
                    float v2 = d[mt][2 * hh + 1][lohi * 2];
                    float v3 = d[mt][2 * hh + 1][lohi * 2 + 1];
                    float m = fmaxf(fmaxf(v0, v1), fmaxf(v2, v3));
                    m = fmaxf(m, __shfl_xor_sync(0xffffffffu, m, 1));
                    m = fmaxf(m, __shfl_xor_sync(0xffffffffu, m, 2));
                    float e0 = __expf(v0 - m), e1 = __expf(v1 - m);
                    float e2 = __expf(v2 - m), e3 = __expf(v3 - m);
                    float s = e0 + e1 + e2 + e3;
                    s += __shfl_xor_sync(0xffffffffu, s, 1);
                    s += __shfl_xor_sync(0xffffffffu, s, 2);
                    float inv = 1.f / s;
                    int row = row0 + wm * 32 + mt * 16 + g + lohi * 8;
                    if (row < NROWS) {
                        float* ap = &g_attn[((size_t)row * NH + head) * 16];
                        ap[2 * tig]     = e0 * inv;
                        ap[2 * tig + 1] = e1 * inv;
                        ap[8 + 2 * tig]     = e2 * inv;
                        ap[8 + 2 * tig + 1] = e3 * inv;
                    }
                }
            }
        }
    }
}

// ---------------------------------------------------------------------------
// Kernel C v2: two-phase sampling. Phase 1: one thread per sample computes
// clamped corner indices + combined (attn*bilinear, validity-folded) weights
// into smem. Phase 2: lane = channel-pair, branch-free gathers + FFMA2.
// ---------------------------------------------------------------------------
__global__ __launch_bounds__(256)
void k_sample(float* __restrict__ out)
{
    __shared__ int4   sIdx[256];
    __shared__ float4 sWt[256];
    const int t = threadIdx.x;
    const int bq0 = blockIdx.x * 2;

    // Phase 1: sample s = head*16 + l*4 + p -> coords at g_coord[bq*256 + 2s]
    {
        const int sbq = t >> 7, s = t & 127;
        const int bq = bq0 + sbq;
        const int l = (s >> 2) & 3;
        const int H = c_Hl[l], W = c_Wl[l];
        const int b = bq / NQ;
        float2 xy = *reinterpret_cast<const float2*>(&g_coord[(size_t)bq * 256 + 2 * s]);
        float w = g_attn[(size_t)bq * 128 + s];
        float x0f = floorf(xy.x), y0f = floorf(xy.y);
        int x0 = (int)x0f, y0 = (int)y0f;
        float wx1 = xy.x - x0f, wy1 = xy.y - y0f;
        float wx0 = 1.f - wx1, wy0 = 1.f - wy1;
        bool xin0 = (x0 >= 0) & (x0 < W);
        bool xin1 = (x0 >= -1) & (x0 < W - 1);
        bool yin0 = (y0 >= 0) & (y0 < H);
        bool yin1 = (y0 >= -1) & (y0 < H - 1);
        int xc0 = min(max(x0, 0), W - 1), xc1 = min(max(x0 + 1, 0), W - 1);
        int yc0 = min(max(y0, 0), H - 1), yc1 = min(max(y0 + 1, 0), H - 1);
        int base = b * NV + c_start[l];
        int r0 = base + yc0 * W, r1 = base + yc1 * W;
        sIdx[t] = make_int4(r0 + xc0, r0 + xc1, r1 + xc0, r1 + xc1);
        sWt[t] = make_float4(
            (xin0 & yin0) ? w * wy0 * wx0 : 0.f,
            (xin1 & yin0) ? w * wy0 * wx1 : 0.f,
            (xin0 & yin1) ? w * wy1 * wx0 : 0.f,
            (xin1 & yin1) ? w * wy1 * wx1 : 0.f);
    }
    __syncthreads();

    // Phase 2: gather + accumulate
    const int sbq = t >> 7, wt = t & 127;
    const int head = wt >> 4, dpair = wt & 15;
    const int chOff = head * 16 + dpair;
    const int bq = bq0 + sbq;
    const int sb = sbq * 128 + head * 16;

    unsigned long long acc;
    { float z = 0.f; PACK2(acc, z, z); }
    #pragma unroll 4
    for (int pt = 0; pt < 16; pt++) {
        int4 idx = sIdx[sb + pt];
        float4 w = sWt[sb + pt];
        float2 v0 = __half22float2(g_vh2[(size_t)idx.x * 128 + chOff]);
        float2 v1 = __half22float2(g_vh2[(size_t)idx.y * 128 + chOff]);
        float2 v2 = __half22float2(g_vh2[(size_t)idx.z * 128 + chOff]);
        float2 v3 = __half22float2(g_vh2[(size_t)idx.w * 128 + chOff]);
        unsigned long long vv, w2;
        PACK2(vv, v0.x, v0.y); PACK2(w2, w.x, w.x); FFMA2(acc, vv, w2);
        PACK2(vv, v1.x, v1.y); PACK2(w2, w.y, w.y); FFMA2(acc, vv, w2);
        PACK2(vv, v2.x, v2.y); PACK2(w2, w.z, w.z); FFMA2(acc, vv, w2);
        PACK2(vv, v3.x, v3.y); PACK2(w2, w.w, w.w); FFMA2(acc, vv, w2);
    }
    float ax, ay; UNPACK2(ax, ay, acc);
    *reinterpret_cast<float2*>(&out[(size_t)bq * 256 + chOff * 2]) = make_float2(ax, ay);
}

// ---------------------------------------------------------------------------
extern "C" void kernel_launch(void* const* d_in, const int* in_sizes, int n_in,
                              void* d_out, int out_size)
{
    const float* query = (const float*)d_in[0];
    const float* value = (const float*)d_in[1];
    const float* qpos  = (const float*)d_in[2];
    const float* refp  = (const float*)d_in[3];
    const float* Wval  = (const float*)d_in[4];
    const float* bval  = (const float*)d_in[5];
    const float* Woff  = (const float*)d_in[6];
    const float* boff  = (const float*)d_in[7];
    const float* Wattn = (const float*)d_in[8];
    const float* battn = (const float*)d_in[9];
    float* out = (float*)d_out;

    k_prep<<<160, 256>>>(Wval, Woff, Wattn);
    k_vproj<<<((VROWS + 127) / 128) * 4, 256>>>(value, bval);
    k_offattn<<<((NROWS + 127) / 128) * 6, 256>>>(query, qpos, refp, boff, battn);
    k_sample<<<NROWS / 2, 256>>>(out);
}

// round 16
// speedup vs baseline: 3.7993x; 1.0171x over previous
#include <cuda_runtime.h>
#include <cuda_fp16.h>
#include <cstdint>

#define BS 2
#define NQ 10000
#define NV 19560
#define NROWS (BS*NQ)           // 20000
#define VROWS (BS*NV)           // 39120
#define NH 8

__device__ __constant__ int c_Hl[4]    = {92, 46, 23, 12};
__device__ __constant__ int c_Wl[4]    = {160, 80, 40, 20};
__device__ __constant__ int c_start[4] = {0, 14720, 18400, 19320};

__device__ float g_v[(size_t)VROWS * 256];       // projected value fp32
__device__ float g_coord[(size_t)NROWS * 256];
__device__ float g_attn[(size_t)NROWS * NH * 16];
__device__ __half g_wtv[256 * 256];              // W_val^T  [n][k]
__device__ __half g_wt[384 * 256];               // [W_off^T ; W_attn^T]  [n][k]

#define PACK2(d, lo, hi) asm("mov.b64 %0, {%1, %2};" : "=l"(d) : "f"(lo), "f"(hi))
#define UNPACK2(lo, hi, d) asm("mov.b64 {%0, %1}, %2;" : "=f"(lo), "=f"(hi) : "l"(d))
#define FFMA2(c, a, b) asm("fma.rn.f32x2 %0, %1, %2, %0;" : "+l"(c) : "l"(a), "l"(b))

__device__ __forceinline__ uint32_t sm32(const void* p) {
    return (uint32_t)__cvta_generic_to_shared(p);
}
__device__ __forceinline__ uint32_t h2u(__half2 h) { return *reinterpret_cast<uint32_t*>(&h); }
__device__ __forceinline__ void ldsm4(uint32_t* r, uint32_t a) {
    asm volatile("ldmatrix.sync.aligned.m8n8.x4.shared.b16 {%0,%1,%2,%3}, [%4];"
        : "=r"(r[0]), "=r"(r[1]), "=r"(r[2]), "=r"(r[3]) : "r"(a));
}
__device__ __forceinline__ void mma16816(float* d, const uint32_t* a, uint32_t b0, uint32_t b1) {
    asm volatile("mma.sync.aligned.m16n8k16.row.col.f32.f16.f16.f32 "
        "{%0,%1,%2,%3},{%4,%5,%6,%7},{%8,%9},{%0,%1,%2,%3};"
        : "+f"(d[0]), "+f"(d[1]), "+f"(d[2]), "+f"(d[3])
        : "r"(a[0]), "r"(a[1]), "r"(a[2]), "r"(a[3]), "r"(b0), "r"(b1));
}

// ---------------------------------------------------------------------------
// Prep: transpose+convert weights to fp16 [n][k]. 160 blocks x 256 thr.
// ---------------------------------------------------------------------------
__global__ __launch_bounds__(256)
void k_prep(const float* __restrict__ Wv, const float* __restrict__ Wo,
            const float* __restrict__ Wa)
{
    __shared__ float tile[32][33];
    int bid = blockIdx.x;
    const float* src; __half* dst; int srcld, tk, tn;
    if (bid < 64)       { src = Wv; dst = g_wtv;           srcld = 256; tk = bid >> 3; tn = bid & 7; }
    else if (bid < 128) { bid -= 64;  src = Wo; dst = g_wt; srcld = 256; tk = bid >> 3; tn = bid & 7; }
    else                { bid -= 128; src = Wa; dst = g_wt + 256 * 256; srcld = 128; tk = bid >> 2; tn = bid & 3; }
    int tx = threadIdx.x & 31, ty = threadIdx.x >> 5;
    #pragma unroll
    for (int i = 0; i < 4; i++)
        tile[ty + i * 8][tx] = src[(size_t)(tk * 32 + ty + i * 8) * srcld + tn * 32 + tx];
    __syncthreads();
    #pragma unroll
    for (int i = 0; i < 4; i++)
        dst[(size_t)(tn * 32 + ty + i * 8) * 256 + tk * 32 + tx] = __float2half(tile[tx][ty + i * 8]);
}

#define SA_STR 72
#define SB_STR 72
#define NB_V ((VROWS + 127) / 128 * 4)   // 1224
#define NB_O ((NROWS + 127) / 128 * 6)   // 942

// ---------------------------------------------------------------------------
// vproj body: 128x64 tensor-core GEMM, fp32 epilogue to g_v.
// ---------------------------------------------------------------------------
__device__ __forceinline__
void vproj_body(int bid, __half (*sA)[SA_STR], __half (*sB)[SB_STR],
                const float* __restrict__ value, const float* __restrict__ bv)
{
    const int t = threadIdx.x;
    const int lane = t & 31, wid = t >> 5;
    const int wm = wid & 3, wn = wid >> 2;
    const int row0 = (bid >> 2) * 128;
    const int col0 = (bid & 3) * 64;
    const int g = lane >> 2, tig = lane & 3;

    float d[2][4][4];
    #pragma unroll
    for (int nt = 0; nt < 4; nt++) {
        float b0v = bv[col0 + wn * 32 + nt * 8 + 2 * tig];
        float b1v = bv[col0 + wn * 32 + nt * 8 + 2 * tig + 1];
        #pragma unroll
        for (int mt = 0; mt < 2; mt++) {
            d[mt][nt][0] = b0v; d[mt][nt][1] = b1v;
            d[mt][nt][2] = b0v; d[mt][nt][3] = b1v;
        }
    }

    const int fr = t >> 1, fseg = (t & 1) * 32;
    const int fn = t >> 2, fbs = (t & 3) * 16;

    for (int kc = 0; kc < 256; kc += 64) {
        {
            int grow = row0 + fr;
            uint32_t hw[16];
            if (grow < VROWS) {
                const float4* src = reinterpret_cast<const float4*>(
                    &value[(size_t)grow * 256 + kc + fseg]);
                #pragma unroll
                for (int i = 0; i < 8; i++) {
                    float4 v = src[i];
                    hw[2 * i]     = h2u(__floats2half2_rn(v.x, v.y));
                    hw[2 * i + 1] = h2u(__floats2half2_rn(v.z, v.w));
                }
            } else {
                #pragma unroll
                for (int i = 0; i < 16; i++) hw[i] = 0u;
            }
            uint4* dst = reinterpret_cast<uint4*>(&sA[fr][fseg]);
            #pragma unroll
            for (int j = 0; j < 4; j++)
                dst[j] = make_uint4(hw[4*j], hw[4*j+1], hw[4*j+2], hw[4*j+3]);
        }
        {
            const uint4* wsrc = reinterpret_cast<const uint4*>(
                &g_wtv[(size_t)(col0 + fn) * 256 + kc + fbs]);
            uint4* dst = reinterpret_cast<uint4*>(&sB[fn][fbs]);
            dst[0] = wsrc[0]; dst[1] = wsrc[1];
        }
        __syncthreads();

        #pragma unroll
        for (int k0 = 0; k0 < 64; k0 += 16) {
            uint32_t a[2][4], b[2][4];
            #pragma unroll
            for (int mt = 0; mt < 2; mt++)
                ldsm4(a[mt], sm32(&sA[wm * 32 + mt * 16 + (lane & 15)][k0 + (lane >> 4) * 8]));
            #pragma unroll
            for (int np = 0; np < 2; np++)
                ldsm4(b[np], sm32(&sB[wn * 32 + np * 16 + (lane & 7) + ((lane >> 4) << 3)]
                                     [k0 + ((lane >> 3) & 1) * 8]));
            #pragma unroll
            for (int mt = 0; mt < 2; mt++)
                #pragma unroll
                for (int nt = 0; nt < 4; nt++)
                    mma16816(d[mt][nt], a[mt], b[nt >> 1][(nt & 1) * 2], b[nt >> 1][(nt & 1) * 2 + 1]);
        }
        __syncthreads();
    }

    #pragma unroll
    for (int mt = 0; mt < 2; mt++)
        #pragma unroll
        for (int nt = 0; nt < 4; nt++) {
            int col = col0 + wn * 32 + nt * 8 + 2 * tig;
            int rA = row0 + wm * 32 + mt * 16 + g;
            int rB = rA + 8;
            if (rA < VROWS)
                *reinterpret_cast<float2*>(&g_v[(size_t)rA * 256 + col]) =
                    make_float2(d[mt][nt][0], d[mt][nt][1]);
            if (rB < VROWS)
                *reinterpret_cast<float2*>(&g_v[(size_t)rB * 256 + col]) =
                    make_float2(d[mt][nt][2], d[mt][nt][3]);
        }
}

// ---------------------------------------------------------------------------
// offattn body: q=query+qpos; [off|attn] GEMM + fused epilogues.
// ---------------------------------------------------------------------------
__device__ __forceinline__
void offattn_body(int bid, __half (*sA)[SA_STR], __half (*sB)[SB_STR],
                  const float* __restrict__ query, const float* __restrict__ qpos,
                  const float* __restrict__ refp,
                  const float* __restrict__ boff, const float* __restrict__ battn)
{
    const int t = threadIdx.x;
    const int lane = t & 31, wid = t >> 5;
    const int wm = wid & 3, wn = wid >> 2;
    const int cb = bid % 6;
    const int row0 = (bid / 6) * 128;
    const int g = lane >> 2, tig = lane & 3;
    const bool is_attn = (cb >= 4);

    float d[2][4][4];
    #pragma unroll
    for (int nt = 0; nt < 4; nt++) {
        int col = cb * 64 + wn * 32 + nt * 8 + 2 * tig;
        float b0v = is_attn ? battn[col - 256] : boff[col];
        float b1v = is_attn ? battn[col - 255] : boff[col + 1];
        #pragma unroll
        for (int mt = 0; mt < 2; mt++) {
            d[mt][nt][0] = b0v; d[mt][nt][1] = b1v;
            d[mt][nt][2] = b0v; d[mt][nt][3] = b1v;
        }
    }

    const int fr = t >> 1, fseg = (t & 1) * 32;
    const int fn = t >> 2, fbs = (t & 3) * 16;

    for (int kc = 0; kc < 256; kc += 64) {
        {
            int grow = row0 + fr;
            uint32_t hw[16];
            if (grow < NROWS) {
                const float4* s1 = reinterpret_cast<const float4*>(
                    &query[(size_t)grow * 256 + kc + fseg]);
                const float4* s2 = reinterpret_cast<const float4*>(
                    &qpos[(size_t)grow * 256 + kc + fseg]);
                #pragma unroll
                for (int i = 0; i < 8; i++) {
                    float4 v = s1[i], u = s2[i];
                    hw[2 * i]     = h2u(__floats2half2_rn(v.x + u.x, v.y + u.y));
                    hw[2 * i + 1] = h2u(__floats2half2_rn(v.z + u.z, v.w + u.w));
                }
            } else {
                #pragma unroll
                for (int i = 0; i < 16; i++) hw[i] = 0u;
            }
            uint4* dst = reinterpret_cast<uint4*>(&sA[fr][fseg]);
            #pragma unroll
            for (int j = 0; j < 4; j++)
                dst[j] = make_uint4(hw[4*j], hw[4*j+1], hw[4*j+2], hw[4*j+3]);
        }
        {
            const uint4* wsrc = reinterpret_cast<const uint4*>(
                &g_wt[(size_t)(cb * 64 + fn) * 256 + kc + fbs]);
            uint4* dst = reinterpret_cast<uint4*>(&sB[fn][fbs]);
            dst[0] = wsrc[0]; dst[1] = wsrc[1];
        }
        __syncthreads();

        #pragma unroll
        for (int k0 = 0; k0 < 64; k0 += 16) {
            uint32_t a[2][4], b[2][4];
            #pragma unroll
            for (int mt = 0; mt < 2; mt++)
                ldsm4(a[mt], sm32(&sA[wm * 32 + mt * 16 + (lane & 15)][k0 + (lane >> 4) * 8]));
            #pragma unroll
            for (int np = 0; np < 2; np++)
                ldsm4(b[np], sm32(&sB[wn * 32 + np * 16 + (lane & 7) + ((lane >> 4) << 3)]
                                     [k0 + ((lane >> 3) & 1) * 8]));
            #pragma unroll
            for (int mt = 0; mt < 2; mt++)
                #pragma unroll
                for (int nt = 0; nt < 4; nt++)
                    mma16816(d[mt][nt], a[mt], b[nt >> 1][(nt & 1) * 2], b[nt >> 1][(nt & 1) * 2 + 1]);
        }
        __syncthreads();
    }

    if (!is_attn) {
        #pragma unroll
        for (int nt = 0; nt < 4; nt++) {
            #pragma unroll
            for (int cp = 0; cp < 2; cp++) {
                int col = cb * 64 + wn * 32 + nt * 8 + 2 * tig + cp;
                int cc = col & 1, p = (col >> 1) & 3, l = (col >> 3) & 3;
                float norm = (cc == 0) ? (float)c_Wl[l] : (float)c_Hl[l];
                #pragma unroll
                for (int mt = 0; mt < 2; mt++) {
                    int rA = row0 + wm * 32 + mt * 16 + g;
                    int rB = rA + 8;
                    if (rA < NROWS) {
                        float rv = refp[(size_t)rA * 8 + p * 2 + cc];
                        g_coord[(size_t)rA * 256 + col] = rv * norm + d[mt][nt][cp] - 0.5f;
                    }
                    if (rB < NROWS) {
                        float rv = refp[(size_t)rB * 8 + p * 2 + cc];
                        g_coord[(size_t)rB * 256 + col] = rv * norm + d[mt][nt][2 + cp] - 0.5f;
                    }
                }
            }
        }
    } else {
        #pragma unroll
        for (int hh = 0; hh < 2; hh++) {
            int head = (cb - 4) * 4 + wn * 2 + hh;
            #pragma unroll
            for (int mt = 0; mt < 2; mt++) {
                #pragma unroll
                for (int lohi = 0; lohi < 2; lohi++) {
                    float v0 = d[mt][2 * hh][lohi * 2];
                    float v1 = d[mt][2 * hh][lohi * 2 + 1];
                    float v2 = d[mt][2 * hh + 1][lohi * 2];
                    float v3 = d[mt][2 * hh + 1][lohi * 2 + 1];
                    float m = fmaxf(fmaxf(v0, v1), fmaxf(v2, v3));
                    m = fmaxf(m, __shfl_xor_sync(0xffffffffu, m, 1));
                    m = fmaxf(m, __shfl_xor_sync(0xffffffffu, m, 2));
                    float e0 = __expf(v0 - m), e1 = __expf(v1 - m);
                    float e2 = __expf(v2 - m), e3 = __expf(v3 - m);
                    float s = e0 + e1 + e2 + e3;
                    s += __shfl_xor_sync(0xffffffffu, s, 1);
                    s += __shfl_xor_sync(0xffffffffu, s, 2);
                    float inv = 1.f / s;
                    int row = row0 + wm * 32 + mt * 16 + g + lohi * 8;
                    if (row < NROWS) {
                        float* ap = &g_attn[((size_t)row * NH + head) * 16];
                        ap[2 * tig]     = e0 * inv;
                        ap[2 * tig + 1] = e1 * inv;
                        ap[8 + 2 * tig]     = e2 * inv;
                        ap[8 + 2 * tig + 1] = e3 * inv;
                    }
                }
            }
        }
    }
}

// ---------------------------------------------------------------------------
// Merged GEMM kernel: blocks [0, NB_V) -> vproj, [NB_V, NB_V+NB_O) -> offattn.
// Co-schedules the two independent GEMMs across SMs.
// ---------------------------------------------------------------------------
__global__ __launch_bounds__(256)
void k_gemm(const float* __restrict__ value, const float* __restrict__ bv,
            const float* __restrict__ query, const float* __restrict__ qpos,
            const float* __restrict__ refp,
            const float* __restrict__ boff, const float* __restrict__ battn)
{
    __shared__ __half sA[128][SA_STR];
    __shared__ __half sB[64][SB_STR];
    int bid = blockIdx.x;
    if (bid < NB_V) vproj_body(bid, sA, sB, value, bv);
    else            offattn_body(bid - NB_V, sA, sB, query, qpos, refp, boff, battn);
}

// ---------------------------------------------------------------------------
// Kernel C v3: two-phase sampling, fp32 LDG.128 gathers.
// 4 bq per block; phase 2: 8 lanes per head, lane = 4 channels.
// ---------------------------------------------------------------------------
__global__ __launch_bounds__(256)
void k_sample(float* __restrict__ out)
{
    __shared__ int4   sIdx[512];
    __shared__ float4 sWt[512];
    const int t = threadIdx.x;
    const int bq0 = blockIdx.x * 4;

    // Phase 1: 512 samples, 2 per thread. Sample s = head*16 + l*4 + p.
    #pragma unroll
    for (int i = 0; i < 2; i++) {
        const int sid = t + i * 256;
        const int sbq = sid >> 7, s = sid & 127;
        const int bq = bq0 + sbq;
        const int l = (s >> 2) & 3;
        const int H = c_Hl[l], W = c_Wl[l];
        const int b = bq / NQ;
        float2 xy = *reinterpret_cast<const float2*>(&g_coord[(size_t)bq * 256 + 2 * s]);
        float w = g_attn[(size_t)bq * 128 + s];
        float x0f = floorf(xy.x), y0f = floorf(xy.y);
        int x0 = (int)x0f, y0 = (int)y0f;
        float wx1 = xy.x - x0f, wy1 = xy.y - y0f;
        float wx0 = 1.f - wx1, wy0 = 1.f - wy1;
        bool xin0 = (x0 >= 0) & (x0 < W);
        bool xin1 = (x0 >= -1) & (x0 < W - 1);
        bool yin0 = (y0 >= 0) & (y0 < H);
        bool yin1 = (y0 >= -1) & (y0 < H - 1);
        int xc0 = min(max(x0, 0), W - 1), xc1 = min(max(x0 + 1, 0), W - 1);
        int yc0 = min(max(y0, 0), H - 1), yc1 = min(max(y0 + 1, 0), H - 1);
        int base = b * NV + c_start[l];
        int r0 = base + yc0 * W, r1 = base + yc1 * W;
        sIdx[sid] = make_int4(r0 + xc0, r0 + xc1, r1 + xc0, r1 + xc1);
        sWt[sid] = make_float4(
            (xin0 & yin0) ? w * wy0 * wx0 : 0.f,
            (xin1 & yin0) ? w * wy0 * wx1 : 0.f,
            (xin0 & yin1) ? w * wy1 * wx0 : 0.f,
            (xin1 & yin1) ? w * wy1 * wx1 : 0.f);
    }
    __syncthreads();

    // Phase 2: sbq = t>>6; head = (t>>3)&7; lane owns 4 channels.
    const int sbq = t >> 6, wt = t & 63;
    const int head = wt >> 3, l8 = wt & 7;
    const int chOff = head * 32 + l8 * 4;
    const int bq = bq0 + sbq;
    const int sb = sbq * 128 + head * 16;

    unsigned long long a0, a1;
    { float z = 0.f; PACK2(a0, z, z); PACK2(a1, z, z); }
    #pragma unroll 4
    for (int pt = 0; pt < 16; pt++) {
        int4 idx = sIdx[sb + pt];
        float4 w = sWt[sb + pt];
        unsigned long long w2, vv0, vv1;
        float4 v;
        v = *reinterpret_cast<const float4*>(&g_v[(size_t)idx.x * 256 + chOff]);
        PACK2(w2, w.x, w.x);
        PACK2(vv0, v.x, v.y); FFMA2(a0, vv0, w2);
        PACK2(vv1, v.z, v.w); FFMA2(a1, vv1, w2);
        v = *reinterpret_cast<const float4*>(&g_v[(size_t)idx.y * 256 + chOff]);
        PACK2(w2, w.y, w.y);
        PACK2(vv0, v.x, v.y); FFMA2(a0, vv0, w2);
        PACK2(vv1, v.z, v.w); FFMA2(a1, vv1, w2);
        v = *reinterpret_cast<const float4*>(&g_v[(size_t)idx.z * 256 + chOff]);
        PACK2(w2, w.z, w.z);
        PACK2(vv0, v.x, v.y); FFMA2(a0, vv0, w2);
        PACK2(vv1, v.z, v.w); FFMA2(a1, vv1, w2);
        v = *reinterpret_cast<const float4*>(&g_v[(size_t)idx.w * 256 + chOff]);
        PACK2(w2, w.w, w.w);
        PACK2(vv0, v.x, v.y); FFMA2(a0, vv0, w2);
        PACK2(vv1, v.z, v.w); FFMA2(a1, vv1, w2);
    }
    float r0, r1, r2, r3;
    UNPACK2(r0, r1, a0); UNPACK2(r2, r3, a1);
    *reinterpret_cast<float4*>(&out[(size_t)bq * 256 + chOff]) = make_float4(r0, r1, r2, r3);
}

// ---------------------------------------------------------------------------
extern "C" void kernel_launch(void* const* d_in, const int* in_sizes, int n_in,
                              void* d_out, int out_size)
{
    const float* query = (const float*)d_in[0];
    const float* value = (const float*)d_in[1];
    const float* qpos  = (const float*)d_in[2];
    const float* refp  = (const float*)d_in[3];
    const float* Wval  = (const float*)d_in[4];
    const float* bval  = (const float*)d_in[5];
    const float* Woff  = (const float*)d_in[6];
    const float* boff  = (const float*)d_in[7];
    const float* Wattn = (const float*)d_in[8];
    const float* battn = (const float*)d_in[9];
    float* out = (float*)d_out;

    k_prep<<<160, 256>>>(Wval, Woff, Wattn);
    k_gemm<<<NB_V + NB_O, 256>>>(value, bval, query, qpos, refp, boff, battn);
    k_sample<<<NROWS / 4, 256>>>(out);
}